// round 4
// baseline (speedup 1.0000x reference)
#include <cuda_runtime.h>
#include <cuda_bf16.h>
#include <math.h>
#include <stdint.h>

// ---------------- problem constants ----------------
#define DIMC   2048
#define NHEADS 2
#define HDIM   1024
#define BATCH  4
#define SEQ    2048
#define M1     (BATCH*SEQ)   // 8192
#define QKVN   (3*DIMC)      // 6144

__device__ __forceinline__ uint32_t smem_u32(const void* p) {
    uint32_t a;
    asm("{ .reg .u64 t; cvta.to.shared.u64 t, %1; cvt.u32.u64 %0, t; }" : "=r"(a) : "l"(p));
    return a;
}

#define CP_ASYNC16(dst, src) \
    asm volatile("cp.async.cg.shared.global [%0], [%1], 16;" :: "r"(dst), "l"(src) : "memory")
#define CP_COMMIT() asm volatile("cp.async.commit_group;" ::: "memory")
#define CP_WAIT1()  asm volatile("cp.async.wait_group 1;" ::: "memory")
#define CP_WAIT0()  asm volatile("cp.async.wait_group 0;" ::: "memory")

#define LDMATRIX_X4(r0, r1, r2, r3, addr) \
    asm volatile("ldmatrix.sync.aligned.m8n8.x4.shared.b16 {%0,%1,%2,%3}, [%4];" \
        : "=r"(r0), "=r"(r1), "=r"(r2), "=r"(r3) : "r"(addr))

// int8 MMA: m16n8k32, s32 accum
#define MMA_S8(c, a, b0, b1) \
    asm volatile("mma.sync.aligned.m16n8k32.row.col.s32.s8.s8.s32 " \
        "{%0,%1,%2,%3}, {%4,%5,%6,%7}, {%8,%9}, {%0,%1,%2,%3};" \
        : "+r"((c)[0]), "+r"((c)[1]), "+r"((c)[2]), "+r"((c)[3]) \
        : "r"((a)[0]), "r"((a)[1]), "r"((a)[2]), "r"((a)[3]), "r"(b0), "r"(b1))

// ---------------- scratch ----------------
__device__ float g_qkv[(size_t)M1 * QKVN];
__device__ float g_s  [(size_t)8 * SEQ * SEQ];
__device__ float g_q  [(size_t)8 * SEQ * HDIM];
__device__ float g_vt [(size_t)8 * HDIM * SEQ];
__device__ float g_vh [(size_t)M1 * DIMC];
__device__ float g_ctab[SEQ * 512];
__device__ float g_stab[SEQ * 512];

// int8 digit arrays (q0, q1)
__device__ __align__(128) int8_t g_x0[(size_t)M1*DIMC],   g_x1[(size_t)M1*DIMC];
__device__ __align__(128) int8_t g_wq0[(size_t)QKVN*DIMC], g_wq1[(size_t)QKVN*DIMC];
__device__ __align__(128) int8_t g_ow0[(size_t)DIMC*DIMC], g_ow1[(size_t)DIMC*DIMC];
__device__ __align__(128) int8_t g_q0[(size_t)8*SEQ*HDIM], g_q1[(size_t)8*SEQ*HDIM];
__device__ __align__(128) int8_t g_k0[(size_t)8*SEQ*HDIM], g_k1[(size_t)8*SEQ*HDIM];
__device__ __align__(128) int8_t g_vt0[(size_t)8*HDIM*SEQ], g_vt1[(size_t)8*HDIM*SEQ];
__device__ __align__(128) int8_t g_p0[(size_t)8*SEQ*SEQ],  g_p1[(size_t)8*SEQ*SEQ];
__device__ __align__(128) int8_t g_vh0[(size_t)M1*DIMC],  g_vh1[(size_t)M1*DIMC];

// per-row scales
__device__ float g_sx[M1], g_swq[QKVN], g_sow[DIMC];
__device__ float g_sq[8*SEQ], g_sk[8*SEQ], g_svt[8*HDIM];
__device__ float g_sp[8*SEQ], g_svh[M1];

// ---------------- RoPE tables ----------------
__global__ void rope_tab_kernel() {
    int idx = blockIdx.x * blockDim.x + threadIdx.x;
    int d = idx & 511, l = idx >> 9;
    double inv = exp((double)(2 * d) * (-9.210340371976184 / 1024.0));
    double th  = (double)l * inv;
    g_ctab[idx] = (float)cos(th);
    g_stab[idx] = (float)sin(th);
}

// ---------------- per-row 2-digit int8 quantization ----------------
__device__ __forceinline__ void qdig(float f, int8_t& d0, int8_t& d1) {
    float r0 = rintf(f);
    float r  = f - r0;
    int q1 = (int)rintf(r * 256.0f);
    q1 = max(-128, min(127, q1));
    d0 = (int8_t)(int)r0;
    d1 = (int8_t)q1;
}

__global__ void quant_rows(const float* __restrict__ in, int K,
                           int8_t* __restrict__ o0, int8_t* __restrict__ o1,
                           float* __restrict__ scale) {
    size_t row = blockIdx.x;
    const float* p = in + row * (size_t)K;
    int t = threadIdx.x;
    float m = 0.f;
    for (int i = t * 4; i < K; i += 1024) {
        float4 v = *(const float4*)(p + i);
        m = fmaxf(m, fmaxf(fmaxf(fabsf(v.x), fabsf(v.y)), fmaxf(fabsf(v.z), fabsf(v.w))));
    }
    __shared__ float red[256];
    red[t] = m; __syncthreads();
    #pragma unroll
    for (int s = 128; s > 0; s >>= 1) { if (t < s) red[t] = fmaxf(red[t], red[t + s]); __syncthreads(); }
    float s = fmaxf(red[0], 1e-30f);
    float inv = 127.0f / s;
    if (t == 0) scale[row] = s * (1.0f / 127.0f);
    for (int i = t * 4; i < K; i += 1024) {
        float4 v = *(const float4*)(p + i);
        char4 c0, c1;
        qdig(v.x * inv, (int8_t&)c0.x, (int8_t&)c1.x);
        qdig(v.y * inv, (int8_t&)c0.y, (int8_t&)c1.y);
        qdig(v.z * inv, (int8_t&)c0.z, (int8_t&)c1.z);
        qdig(v.w * inv, (int8_t&)c0.w, (int8_t&)c1.w);
        *(char4*)(o0 + row * (size_t)K + i) = c0;
        *(char4*)(o1 + row * (size_t)K + i) = c1;
    }
}

// ---------------- RoPE apply (fp32 outputs) ----------------
__global__ void rope_apply(const float* __restrict__ qkv,
                           float* __restrict__ qout,
                           float* __restrict__ kout, float* __restrict__ vout) {
    int idx = blockIdx.x * blockDim.x + threadIdx.x;
    int d = idx & 511;
    int l = (idx >> 9) & (SEQ - 1);
    int h = (idx >> 20) & 1;
    int b = idx >> 21;
    int ti = (l << 9) + d;
    float c = g_ctab[ti], s = g_stab[ti];
    const float* row = qkv + (size_t)(b * SEQ + l) * QKVN;
    int off = h * HDIM + d;
    float q1 = row[off],          q2 = row[off + 512];
    float k1 = row[DIMC + off],   k2 = row[DIMC + off + 512];
    float v1 = row[2*DIMC + off], v2 = row[2*DIMC + off + 512];
    size_t o = (size_t)((b * NHEADS + h) * SEQ + l) * HDIM + d;
    qout[o]       = q1*c - q2*s;
    qout[o + 512] = q1*s + q2*c;
    kout[o]       = k1*c - k2*s;
    kout[o + 512] = k1*s + k2*c;
    vout[o]       = v1;
    vout[o + 512] = v2;
}

// ---------------- V transpose (fp32): qkv(v) -> Vt[b,h,d,l] ----------------
__global__ void vt_kernel(const float* __restrict__ qkv, float* __restrict__ vt) {
    __shared__ float tile[32][33];
    int z = blockIdx.z;
    int b = z >> 1, h = z & 1;
    int l0 = blockIdx.x * 32, d0 = blockIdx.y * 32;
    int tx = threadIdx.x, ty = threadIdx.y;
    #pragma unroll
    for (int j = 0; j < 32; j += 8) {
        int l = l0 + ty + j, d = d0 + tx;
        tile[ty + j][tx] = qkv[(size_t)(b * SEQ + l) * QKVN + 2*DIMC + h*HDIM + d];
    }
    __syncthreads();
    #pragma unroll
    for (int j = 0; j < 32; j += 8) {
        int d = d0 + ty + j, l = l0 + tx;
        vt[((size_t)z * HDIM + d) * SEQ + l] = tile[tx][ty + j];
    }
}

// ---------------- softmax + fused int8 digit quantization ----------------
// p_j = e_j / sum, row scale = (1/sum)/127 -> digits from f = 127*e_j
__global__ void softmax_quant(const float* __restrict__ S,
                              int8_t* __restrict__ P0, int8_t* __restrict__ P1,
                              float* __restrict__ sp) {
    size_t row = blockIdx.x;
    const float* p = S + row * (size_t)SEQ;
    int t = threadIdx.x;
    float v[8];
    float4 v0 = *(const float4*)(p + t * 8);
    float4 v1 = *(const float4*)(p + t * 8 + 4);
    v[0]=v0.x; v[1]=v0.y; v[2]=v0.z; v[3]=v0.w;
    v[4]=v1.x; v[5]=v1.y; v[6]=v1.z; v[7]=v1.w;
    float m = v[0];
    #pragma unroll
    for (int j = 1; j < 8; j++) m = fmaxf(m, v[j]);
    __shared__ float red[256];
    red[t] = m; __syncthreads();
    #pragma unroll
    for (int s = 128; s > 0; s >>= 1) { if (t < s) red[t] = fmaxf(red[t], red[t + s]); __syncthreads(); }
    float mx = red[0]; __syncthreads();
    float sum = 0.f;
    #pragma unroll
    for (int j = 0; j < 8; j++) { v[j] = expf(v[j] - mx); sum += v[j]; }
    red[t] = sum; __syncthreads();
    #pragma unroll
    for (int s = 128; s > 0; s >>= 1) { if (t < s) red[t] += red[t + s]; __syncthreads(); }
    float inv = 1.0f / red[0];
    if (t == 0) sp[row] = inv * (1.0f / 127.0f);
    char4 c0[2], c1[2];
    #pragma unroll
    for (int j = 0; j < 8; j++) {
        int8_t d0, d1;
        qdig(127.0f * v[j], d0, d1);
        ((int8_t*)c0)[j] = d0;
        ((int8_t*)c1)[j] = d1;
    }
    *(char4*)(P0 + row * SEQ + t * 8)     = c0[0];
    *(char4*)(P0 + row * SEQ + t * 8 + 4) = c0[1];
    *(char4*)(P1 + row * SEQ + t * 8)     = c1[0];
    *(char4*)(P1 + row * SEQ + t * 8 + 4) = c1[1];
}

// ---------------- int8 2-digit warp-IMMA GEMM ----------------
// C = alpha*sa_i*sb_j*((A0B0) + (A0B1+A1B0)/256) (+bias) (+mask)
// A = [M,K] K-major int8 digits, B = [N,K] K-major int8 digits.
// All K/ld/stride units below are b16 units (= 2 int8).
// Block 128x128, 8 warps (4x2), warp tile 32x64; chunk = 32 b16 units = 64 int8.
// CAUSAL: 0 none; 1 fill above-diag tiles -1e9 + add mask; 2 K-limit to (row0+128)/2.
#define KPAD   40
#define MATB   (128 * KPAD * 2)
#define STGB   (4 * MATB)
#define NSTG   3
#define SMEM_MMA (NSTG * STGB)

__device__ __forceinline__ void load_stage_async(uint32_t sbase,
    const uint16_t* A0, const uint16_t* A1,
    const uint16_t* B0, const uint16_t* B1,
    int lda, int ldb, int row0, int col0, int k0)
{
    const int t = threadIdx.x;
    const uint16_t* srcs[4] = {A0, A1, B0, B1};
    #pragma unroll
    for (int i = 0; i < 8; i++) {
        int s = t + i * 256;
        int m   = s >> 9;
        int idx = s & 511;
        int row = idx >> 2;
        int c16 = idx & 3;
        int ld  = (m < 2) ? lda : ldb;
        int r0  = (m < 2) ? row0 : col0;
        const uint16_t* src = srcs[m] + (size_t)(r0 + row) * ld + k0 + c16 * 8;
        uint32_t dst = sbase + m * MATB + row * (KPAD * 2) + c16 * 16;
        CP_ASYNC16(dst, src);
    }
}

template<int CAUSAL>
__global__ void __launch_bounds__(256, 1) gemm_imma(
    const uint16_t* __restrict__ A0, const uint16_t* __restrict__ A1,
    const uint16_t* __restrict__ B0, const uint16_t* __restrict__ B1,
    const float* __restrict__ sa, const float* __restrict__ sb,
    const float* __restrict__ bias, const float* __restrict__ Ms,
    float* __restrict__ C,
    int K, int lda, int ldb, int ldc, int ldm,
    long sA, long sB, long sCo, long sCi, int zdiv,
    long sSa, long sSb, float alpha)
{
    extern __shared__ char smem[];
    const int tid = threadIdx.x;
    const int wid = tid >> 5;
    const int lid = tid & 31;
    const int row0 = blockIdx.y * 128;
    const int col0 = blockIdx.x * 128;
    const int bz = blockIdx.z;

    const size_t zoffC = (size_t)(bz / zdiv) * sCo + (size_t)(bz % zdiv) * sCi;
    A0 += (size_t)bz * sA; A1 += (size_t)bz * sA;
    B0 += (size_t)bz * sB; B1 += (size_t)bz * sB;
    sa += (size_t)bz * sSa; sb += (size_t)bz * sSb;

    if (CAUSAL == 1 && col0 > row0) {
        float* Cz = C + zoffC;
        float4 f = make_float4(-1e9f, -1e9f, -1e9f, -1e9f);
        #pragma unroll
        for (int i = 0; i < 16; i++) {
            int g = tid + i * 256;
            int r = g >> 5, c4 = (g & 31) << 2;
            *(float4*)(Cz + (size_t)(row0 + r) * ldc + col0 + c4) = f;
        }
        return;
    }

    int Keff = (CAUSAL == 2) ? min(K, (row0 + 128) >> 1) : K;
    const int nc = Keff >> 5;

    const uint32_t sb32 = smem_u32(smem);
    const int wm = (wid & 3) * 32;
    const int wn = (wid >> 2) * 64;

    int acc1[2][8][4], acc2[2][8][4];
    #pragma unroll
    for (int mt = 0; mt < 2; mt++)
        #pragma unroll
        for (int nt = 0; nt < 8; nt++)
            #pragma unroll
            for (int r = 0; r < 4; r++) { acc1[mt][nt][r] = 0; acc2[mt][nt][r] = 0; }

    load_stage_async(sb32, A0, A1, B0, B1, lda, ldb, row0, col0, 0);
    CP_COMMIT();
    if (nc > 1) load_stage_async(sb32 + STGB, A0, A1, B0, B1, lda, ldb, row0, col0, 32);
    CP_COMMIT();

    const int lrow = lid & 15;
    const int lcol = (lid >> 4) << 3;

    for (int c = 0; c < nc; c++) {
        if (c + 1 < nc) { CP_WAIT1(); } else { CP_WAIT0(); }
        __syncthreads();
        if (c + 2 < nc) {
            load_stage_async(sb32 + ((c + 2) % NSTG) * STGB, A0, A1, B0, B1,
                             lda, ldb, row0, col0, (c + 2) << 5);
            CP_COMMIT();
        }

        uint32_t stg = sb32 + (c % NSTG) * STGB;
        #pragma unroll
        for (int kk = 0; kk < 32; kk += 16) {    // each kk: one k32-int8 MMA set
            uint32_t a0f[2][4], a1f[2][4], b0f[4][4], b1f[4][4];
            #pragma unroll
            for (int mt = 0; mt < 2; mt++) {
                uint32_t ra = stg + ((wm + mt * 16 + lrow) * KPAD + kk + lcol) * 2;
                LDMATRIX_X4(a0f[mt][0], a0f[mt][1], a0f[mt][2], a0f[mt][3], ra);
                LDMATRIX_X4(a1f[mt][0], a1f[mt][1], a1f[mt][2], a1f[mt][3], ra + MATB);
            }
            #pragma unroll
            for (int g = 0; g < 4; g++) {
                uint32_t rb = stg + 2 * MATB + ((wn + g * 16 + lrow) * KPAD + kk + lcol) * 2;
                LDMATRIX_X4(b0f[g][0], b0f[g][1], b0f[g][2], b0f[g][3], rb);
                LDMATRIX_X4(b1f[g][0], b1f[g][1], b1f[g][2], b1f[g][3], rb + MATB);
            }
            #pragma unroll
            for (int mt = 0; mt < 2; mt++)
                #pragma unroll
                for (int nt = 0; nt < 8; nt++) {
                    int g = nt >> 1, o = nt & 1;
                    MMA_S8(acc1[mt][nt], a0f[mt], b0f[g][o], b0f[g][o + 2]);
                    MMA_S8(acc2[mt][nt], a0f[mt], b1f[g][o], b1f[g][o + 2]);
                    MMA_S8(acc2[mt][nt], a1f[mt], b0f[g][o], b0f[g][o + 2]);
                }
        }
        __syncthreads();
    }

    // ---------------- epilogue ----------------
    float sav[2][2];
    #pragma unroll
    for (int mt = 0; mt < 2; mt++)
        #pragma unroll
        for (int half = 0; half < 2; half++)
            sav[mt][half] = sa[row0 + wm + mt * 16 + (lid >> 2) + half * 8];

    #pragma unroll
    for (int mt = 0; mt < 2; mt++) {
        #pragma unroll
        for (int nt = 0; nt < 8; nt++) {
            int gr0 = row0 + wm + mt * 16 + (lid >> 2);
            int gc  = col0 + wn + nt * 8 + (lid & 3) * 2;
            float sb0 = sb[gc] * alpha, sb1 = sb[gc + 1] * alpha;
            float bb0 = 0.f, bb1 = 0.f;
            if (bias) { bb0 = bias[gc]; bb1 = bias[gc + 1]; }
            #pragma unroll
            for (int half = 0; half < 2; half++) {
                int gr = gr0 + half * 8;
                float m0 = (float)acc1[mt][nt][2*half]     + (float)acc2[mt][nt][2*half]     * (1.0f/256.0f);
                float m1 = (float)acc1[mt][nt][2*half + 1] + (float)acc2[mt][nt][2*half + 1] * (1.0f/256.0f);
                float v0 = m0 * sav[mt][half] * sb0 + bb0;
                float v1 = m1 * sav[mt][half] * sb1 + bb1;
                if (CAUSAL == 1) {
                    const float* mp = Ms + (size_t)gr * ldm + gc;
                    v0 += mp[0]; v1 += mp[1];
                }
                float* Cp = C + zoffC + (size_t)gr * ldc + gc;
                *(float2*)Cp = make_float2(v0, v1);
            }
        }
    }
}

// ---------------- launch ----------------
extern "C" void kernel_launch(void* const* d_in, const int* in_sizes, int n_in,
                              void* d_out, int out_size) {
    const float* x      = (const float*)d_in[0];
    const float* mask   = (const float*)d_in[1];
    const float* Wqkv_w = (const float*)d_in[2];
    const float* Wqkv_b = (const float*)d_in[3];
    const float* out_w  = (const float*)d_in[4];
    const float* out_b  = (const float*)d_in[5];

    float* out  = (float*)d_out;
    float* kout = out  + (size_t)M1 * DIMC;
    float* vout = kout + (size_t)8 * SEQ * HDIM;

    float *qkv, *S, *qf, *vtf, *vhf;
    int8_t *x0,*x1,*wq0,*wq1,*ow0,*ow1,*q0,*q1,*k0,*k1,*vt0,*vt1,*p0,*p1,*vh0,*vh1;
    float *sx,*swq,*sow,*sq,*sk,*svt,*sp,*svh;
    cudaGetSymbolAddress((void**)&qkv, g_qkv);
    cudaGetSymbolAddress((void**)&S,   g_s);
    cudaGetSymbolAddress((void**)&qf,  g_q);
    cudaGetSymbolAddress((void**)&vtf, g_vt);
    cudaGetSymbolAddress((void**)&vhf, g_vh);
    cudaGetSymbolAddress((void**)&x0,  g_x0);  cudaGetSymbolAddress((void**)&x1,  g_x1);
    cudaGetSymbolAddress((void**)&wq0, g_wq0); cudaGetSymbolAddress((void**)&wq1, g_wq1);
    cudaGetSymbolAddress((void**)&ow0, g_ow0); cudaGetSymbolAddress((void**)&ow1, g_ow1);
    cudaGetSymbolAddress((void**)&q0,  g_q0);  cudaGetSymbolAddress((void**)&q1,  g_q1);
    cudaGetSymbolAddress((void**)&k0,  g_k0);  cudaGetSymbolAddress((void**)&k1,  g_k1);
    cudaGetSymbolAddress((void**)&vt0, g_vt0); cudaGetSymbolAddress((void**)&vt1, g_vt1);
    cudaGetSymbolAddress((void**)&p0,  g_p0);  cudaGetSymbolAddress((void**)&p1,  g_p1);
    cudaGetSymbolAddress((void**)&vh0, g_vh0); cudaGetSymbolAddress((void**)&vh1, g_vh1);
    cudaGetSymbolAddress((void**)&sx,  g_sx);  cudaGetSymbolAddress((void**)&swq, g_swq);
    cudaGetSymbolAddress((void**)&sow, g_sow); cudaGetSymbolAddress((void**)&sq,  g_sq);
    cudaGetSymbolAddress((void**)&sk,  g_sk);  cudaGetSymbolAddress((void**)&svt, g_svt);
    cudaGetSymbolAddress((void**)&sp,  g_sp);  cudaGetSymbolAddress((void**)&svh, g_svh);

    cudaFuncSetAttribute(gemm_imma<0>, cudaFuncAttributeMaxDynamicSharedMemorySize, SMEM_MMA);
    cudaFuncSetAttribute(gemm_imma<1>, cudaFuncAttributeMaxDynamicSharedMemorySize, SMEM_MMA);
    cudaFuncSetAttribute(gemm_imma<2>, cudaFuncAttributeMaxDynamicSharedMemorySize, SMEM_MMA);

    // 1) RoPE tables + input quantization
    rope_tab_kernel<<<SEQ, 512>>>();
    quant_rows<<<M1,   256>>>(x,      DIMC, x0,  x1,  sx);
    quant_rows<<<QKVN, 256>>>(Wqkv_w, DIMC, wq0, wq1, swq);
    quant_rows<<<DIMC, 256>>>(out_w,  DIMC, ow0, ow1, sow);

    // 2) QKV = x @ Wqkv^T + b   [8192 x 6144 x 2048], K_b16=1024
    gemm_imma<0><<<dim3(QKVN/128, M1/128, 1), 256, SMEM_MMA>>>(
        (const uint16_t*)x0, (const uint16_t*)x1, (const uint16_t*)wq0, (const uint16_t*)wq1,
        sx, swq, Wqkv_b, nullptr, qkv,
        1024, 1024, 1024, QKVN, 0, 0, 0, 0, 0, 1, 0, 0, 1.0f);

    // 3) RoPE (fp32) + V transpose (fp32)
    rope_apply<<<(8 * SEQ * 512) / 256, 256>>>(qkv, qf, kout, vout);
    vt_kernel<<<dim3(SEQ/32, HDIM/32, 8), dim3(32, 8)>>>(qkv, vtf);

    // 4) quantize q, k, Vt
    quant_rows<<<8*SEQ, 256>>>(qf,   HDIM, q0,  q1,  sq);
    quant_rows<<<8*SEQ, 256>>>(kout, HDIM, k0,  k1,  sk);
    quant_rows<<<8*HDIM,256>>>(vtf,  SEQ,  vt0, vt1, svt);

    // 5) S = (1/32) q @ k^T + mask  per head, causal fill; K_b16=512
    gemm_imma<1><<<dim3(SEQ/128, SEQ/128, 8), 256, SMEM_MMA>>>(
        (const uint16_t*)q0, (const uint16_t*)q1, (const uint16_t*)k0, (const uint16_t*)k1,
        sq, sk, nullptr, mask, S,
        512, 512, 512, SEQ, SEQ,
        (long)SEQ*512, (long)SEQ*512, (long)SEQ*SEQ, 0, 1,
        SEQ, SEQ, 0.03125f);

    // 6) softmax + P digit quantization (fused)
    softmax_quant<<<8 * SEQ, 256>>>(S, p0, p1, sp);

    // 7) VH = P @ V (via Vt), causal K-limit; fp32 out scattered to (B,L,D); K_b16=1024
    gemm_imma<2><<<dim3(HDIM/128, SEQ/128, 8), 256, SMEM_MMA>>>(
        (const uint16_t*)p0, (const uint16_t*)p1, (const uint16_t*)vt0, (const uint16_t*)vt1,
        sp, svt, nullptr, nullptr, vhf,
        1024, 1024, 1024, DIMC, 0,
        (long)SEQ*1024, (long)HDIM*1024, (long)SEQ*DIMC, (long)HDIM, NHEADS,
        SEQ, HDIM, 1.0f);

    // 8) quantize VH, then out = VH @ out_w^T + out_b  [8192 x 2048 x 2048]
    quant_rows<<<M1, 256>>>(vhf, DIMC, vh0, vh1, svh);
    gemm_imma<0><<<dim3(DIMC/128, M1/128, 1), 256, SMEM_MMA>>>(
        (const uint16_t*)vh0, (const uint16_t*)vh1, (const uint16_t*)ow0, (const uint16_t*)ow1,
        svh, sow, out_b, nullptr, out,
        1024, 1024, 1024, DIMC, 0, 0, 0, 0, 0, 1, 0, 0, 1.0f);
}

// round 5
// speedup vs baseline: 1.8670x; 1.8670x over previous
#include <cuda_runtime.h>
#include <cuda_bf16.h>
#include <math.h>
#include <stdint.h>

// ---------------- problem constants ----------------
#define DIMC   2048
#define NHEADS 2
#define HDIM   1024
#define BATCH  4
#define SEQ    2048
#define M1     (BATCH*SEQ)   // 8192
#define QKVN   (3*DIMC)      // 6144

__device__ __forceinline__ uint32_t smem_u32(const void* p) {
    uint32_t a;
    asm("{ .reg .u64 t; cvta.to.shared.u64 t, %1; cvt.u32.u64 %0, t; }" : "=r"(a) : "l"(p));
    return a;
}
__device__ __forceinline__ void split1(float v, __nv_bfloat16& h, __nv_bfloat16& l) {
    h = __float2bfloat16(v);
    l = __float2bfloat16(v - __bfloat162float(h));
}

#define CP_ASYNC16(dst, src) \
    asm volatile("cp.async.cg.shared.global [%0], [%1], 16;" :: "r"(dst), "l"(src) : "memory")
#define CP_COMMIT() asm volatile("cp.async.commit_group;" ::: "memory")
#define CP_WAIT1()  asm volatile("cp.async.wait_group 1;" ::: "memory")
#define CP_WAIT2()  asm volatile("cp.async.wait_group 2;" ::: "memory")

#define LDMATRIX_X4(r0, r1, r2, r3, addr) \
    asm volatile("ldmatrix.sync.aligned.m8n8.x4.shared.b16 {%0,%1,%2,%3}, [%4];" \
        : "=r"(r0), "=r"(r1), "=r"(r2), "=r"(r3) : "r"(addr))

#define MMA_BF16(c, a, b0, b1) \
    asm volatile("mma.sync.aligned.m16n8k16.row.col.f32.bf16.bf16.f32 " \
        "{%0,%1,%2,%3}, {%4,%5,%6,%7}, {%8,%9}, {%0,%1,%2,%3};" \
        : "+f"((c)[0]), "+f"((c)[1]), "+f"((c)[2]), "+f"((c)[3]) \
        : "r"((a)[0]), "r"((a)[1]), "r"((a)[2]), "r"((a)[3]), "r"(b0), "r"(b1))

// ---------------- scratch ----------------
__device__ float g_qkv[(size_t)M1 * QKVN];
__device__ float g_s  [(size_t)8 * SEQ * SEQ];
__device__ float g_ctab[SEQ * 512];
__device__ float g_stab[SEQ * 512];
__device__ __align__(128) __nv_bfloat16 g_xh[(size_t)M1*DIMC],  g_xl[(size_t)M1*DIMC];
__device__ __align__(128) __nv_bfloat16 g_wqh[(size_t)QKVN*DIMC], g_wql[(size_t)QKVN*DIMC];
__device__ __align__(128) __nv_bfloat16 g_owh[(size_t)DIMC*DIMC], g_owl[(size_t)DIMC*DIMC];
__device__ __align__(128) __nv_bfloat16 g_qh[(size_t)8*SEQ*HDIM], g_ql[(size_t)8*SEQ*HDIM];
__device__ __align__(128) __nv_bfloat16 g_kh[(size_t)8*SEQ*HDIM], g_kl[(size_t)8*SEQ*HDIM];
__device__ __align__(128) __nv_bfloat16 g_vth[(size_t)8*HDIM*SEQ], g_vtl[(size_t)8*HDIM*SEQ];
__device__ __align__(128) __nv_bfloat16 g_ph[(size_t)8*SEQ*SEQ],  g_pl[(size_t)8*SEQ*SEQ];
__device__ __align__(128) __nv_bfloat16 g_vhh[(size_t)M1*DIMC],  g_vhl[(size_t)M1*DIMC];

// ---------------- RoPE tables ----------------
__global__ void rope_tab_kernel() {
    int idx = blockIdx.x * blockDim.x + threadIdx.x;
    int d = idx & 511, l = idx >> 9;
    double inv = exp((double)(2 * d) * (-9.210340371976184 / 1024.0));
    double th  = (double)l * inv;
    g_ctab[idx] = (float)cos(th);
    g_stab[idx] = (float)sin(th);
}

// ---------------- fp32 -> bf16 hi/lo split ----------------
__global__ void conv_split(const float* __restrict__ in,
                           __nv_bfloat16* __restrict__ oh, __nv_bfloat16* __restrict__ ol) {
    int i = blockIdx.x * 256 + threadIdx.x;
    float4 v = ((const float4*)in)[i];
    union { __nv_bfloat16 b[4]; uint2 u; } H, L;
    split1(v.x, H.b[0], L.b[0]); split1(v.y, H.b[1], L.b[1]);
    split1(v.z, H.b[2], L.b[2]); split1(v.w, H.b[3], L.b[3]);
    ((uint2*)oh)[i] = H.u;
    ((uint2*)ol)[i] = L.u;
}

// ---------------- RoPE apply ----------------
__global__ void rope_apply(const float* __restrict__ qkv,
                           __nv_bfloat16* __restrict__ qh, __nv_bfloat16* __restrict__ ql,
                           __nv_bfloat16* __restrict__ kh, __nv_bfloat16* __restrict__ kl,
                           float* __restrict__ kout, float* __restrict__ vout) {
    int idx = blockIdx.x * blockDim.x + threadIdx.x;
    int d = idx & 511;
    int l = (idx >> 9) & (SEQ - 1);
    int h = (idx >> 20) & 1;
    int b = idx >> 21;
    int ti = (l << 9) + d;
    float c = g_ctab[ti], s = g_stab[ti];
    const float* row = qkv + (size_t)(b * SEQ + l) * QKVN;
    int off = h * HDIM + d;
    float q1 = row[off],          q2 = row[off + 512];
    float k1 = row[DIMC + off],   k2 = row[DIMC + off + 512];
    float v1 = row[2*DIMC + off], v2 = row[2*DIMC + off + 512];
    size_t o = (size_t)((b * NHEADS + h) * SEQ + l) * HDIM + d;
    float rq1 = q1*c - q2*s, rq2 = q1*s + q2*c;
    float rk1 = k1*c - k2*s, rk2 = k1*s + k2*c;
    split1(rq1, qh[o],       ql[o]);
    split1(rq2, qh[o + 512], ql[o + 512]);
    split1(rk1, kh[o],       kl[o]);
    split1(rk2, kh[o + 512], kl[o + 512]);
    kout[o] = rk1; kout[o + 512] = rk2;
    vout[o] = v1;  vout[o + 512] = v2;
}

// ---------------- V transpose + split: qkv(v) -> Vt[b,h,d,l] hi/lo ----------------
__global__ void vt_kernel(const float* __restrict__ qkv,
                          __nv_bfloat16* __restrict__ vth, __nv_bfloat16* __restrict__ vtl) {
    __shared__ float tile[32][33];
    int z = blockIdx.z;
    int b = z >> 1, h = z & 1;
    int l0 = blockIdx.x * 32, d0 = blockIdx.y * 32;
    int tx = threadIdx.x, ty = threadIdx.y;
    #pragma unroll
    for (int j = 0; j < 32; j += 8) {
        int l = l0 + ty + j, d = d0 + tx;
        tile[ty + j][tx] = qkv[(size_t)(b * SEQ + l) * QKVN + 2*DIMC + h*HDIM + d];
    }
    __syncthreads();
    #pragma unroll
    for (int j = 0; j < 32; j += 8) {
        int d = d0 + ty + j, l = l0 + tx;
        float v = tile[tx][ty + j];
        size_t o = ((size_t)z * HDIM + d) * SEQ + l;
        split1(v, vth[o], vtl[o]);
    }
}

// ---------------- softmax + split to bf16 hi/lo ----------------
__global__ void softmax_split(const float* __restrict__ S,
                              __nv_bfloat16* __restrict__ Ph, __nv_bfloat16* __restrict__ Pl) {
    size_t row = blockIdx.x;
    const float* p = S + row * (size_t)SEQ;
    int t = threadIdx.x;
    float v[8];
    float4 v0 = *(const float4*)(p + t * 8);
    float4 v1 = *(const float4*)(p + t * 8 + 4);
    v[0]=v0.x; v[1]=v0.y; v[2]=v0.z; v[3]=v0.w;
    v[4]=v1.x; v[5]=v1.y; v[6]=v1.z; v[7]=v1.w;
    float m = v[0];
    #pragma unroll
    for (int j = 1; j < 8; j++) m = fmaxf(m, v[j]);
    __shared__ float red[256];
    red[t] = m; __syncthreads();
    #pragma unroll
    for (int s = 128; s > 0; s >>= 1) { if (t < s) red[t] = fmaxf(red[t], red[t + s]); __syncthreads(); }
    float mx = red[0]; __syncthreads();
    float sum = 0.f;
    #pragma unroll
    for (int j = 0; j < 8; j++) { v[j] = expf(v[j] - mx); sum += v[j]; }
    red[t] = sum; __syncthreads();
    #pragma unroll
    for (int s = 128; s > 0; s >>= 1) { if (t < s) red[t] += red[t + s]; __syncthreads(); }
    float inv = 1.0f / red[0];
    union { __nv_bfloat16 b[8]; uint4 u; } H, L;
    #pragma unroll
    for (int j = 0; j < 8; j++) { v[j] *= inv; split1(v[j], H.b[j], L.b[j]); }
    *(uint4*)(Ph + row * SEQ + t * 8) = H.u;
    *(uint4*)(Pl + row * SEQ + t * 8) = L.u;
}

// ---------------- warp-MMA split-bf16 GEMM (pipelined) ----------------
// C = alpha*(A@B^T) (+bias) (+mask). A=[M,K] K-major hi/lo, B=[N,K] K-major hi/lo.
// Block 128x128x32, 8 warps (4x2), warp tile 32x64, m16n8k16 bf16, 4-stage cp.async,
// single sync per chunk, fragment double-buffering, GROUP_M=8 rasterization.
#define KPAD   40
#define MATB   (128 * KPAD * 2)
#define STGB   (4 * MATB)
#define NSTG   4
#define SMEM_MMA (NSTG * STGB)

struct Frags { uint32_t aH[2][4], aL[2][4], bH[4][4], bL[4][4]; };

__device__ __forceinline__ void ldfrags(Frags& f, uint32_t stg, int kk,
                                        int wm, int wn, int lrow, int lcol) {
    #pragma unroll
    for (int mt = 0; mt < 2; mt++) {
        uint32_t ra = stg + ((wm + mt * 16 + lrow) * KPAD + kk + lcol) * 2;
        LDMATRIX_X4(f.aH[mt][0], f.aH[mt][1], f.aH[mt][2], f.aH[mt][3], ra);
        LDMATRIX_X4(f.aL[mt][0], f.aL[mt][1], f.aL[mt][2], f.aL[mt][3], ra + MATB);
    }
    #pragma unroll
    for (int g = 0; g < 4; g++) {
        uint32_t rb = stg + 2 * MATB + ((wn + g * 16 + lrow) * KPAD + kk + lcol) * 2;
        LDMATRIX_X4(f.bH[g][0], f.bH[g][1], f.bH[g][2], f.bH[g][3], rb);
        LDMATRIX_X4(f.bL[g][0], f.bL[g][1], f.bL[g][2], f.bL[g][3], rb + MATB);
    }
}

__device__ __forceinline__ void mma_frags(const Frags& f, float acc[2][8][4]) {
    #pragma unroll
    for (int mt = 0; mt < 2; mt++)
        #pragma unroll
        for (int nt = 0; nt < 8; nt++) {
            int g = nt >> 1, o = nt & 1;
            MMA_BF16(acc[mt][nt], f.aH[mt], f.bH[g][o], f.bH[g][o + 2]);
            MMA_BF16(acc[mt][nt], f.aH[mt], f.bL[g][o], f.bL[g][o + 2]);
            MMA_BF16(acc[mt][nt], f.aL[mt], f.bH[g][o], f.bH[g][o + 2]);
        }
}

__device__ __forceinline__ void load_stage_async(uint32_t sbase,
    const __nv_bfloat16* Ah, const __nv_bfloat16* Al,
    const __nv_bfloat16* Bh, const __nv_bfloat16* Bl,
    int lda, int ldb, int row0, int col0, int k0)
{
    const int t = threadIdx.x;
    const __nv_bfloat16* srcs[4] = {Ah, Al, Bh, Bl};
    #pragma unroll
    for (int i = 0; i < 8; i++) {
        int s = t + i * 256;
        int m   = s >> 9;
        int idx = s & 511;
        int row = idx >> 2;
        int c16 = idx & 3;
        int ld  = (m < 2) ? lda : ldb;
        int r0  = (m < 2) ? row0 : col0;
        const __nv_bfloat16* src = srcs[m] + (size_t)(r0 + row) * ld + k0 + c16 * 8;
        uint32_t dst = sbase + m * MATB + row * (KPAD * 2) + c16 * 16;
        CP_ASYNC16(dst, src);
    }
}

template<int CAUSAL, int EPI>
__global__ void __launch_bounds__(256, 1) gemm_mma(
    const __nv_bfloat16* __restrict__ Ah, const __nv_bfloat16* __restrict__ Al,
    const __nv_bfloat16* __restrict__ Bh, const __nv_bfloat16* __restrict__ Bl,
    const float* __restrict__ bias, const float* __restrict__ Ms,
    void* __restrict__ C0, void* __restrict__ C1,
    int K, int lda, int ldb, int ldc, int ldm,
    long sA, long sB, long sCo, long sCi, int zdiv, float alpha)
{
    extern __shared__ char smem[];
    const int tid = threadIdx.x;
    const int lid = tid & 31;
    const int wid = tid >> 5;
    const int bz = blockIdx.z;

    // GROUP_M=8 rasterization
    const int nbx = gridDim.x, nby = gridDim.y;
    int lin = blockIdx.y * nbx + blockIdx.x;
    int grp = lin / (8 * nbx);
    int rem = lin - grp * (8 * nbx);
    int gm  = min(8, nby - grp * 8);
    const int row0 = (grp * 8 + rem % gm) * 128;
    const int col0 = (rem / gm) * 128;

    const size_t zoffC = (size_t)(bz / zdiv) * sCo + (size_t)(bz % zdiv) * sCi;
    Ah += (size_t)bz * sA; Al += (size_t)bz * sA;
    Bh += (size_t)bz * sB; Bl += (size_t)bz * sB;

    if (CAUSAL == 1 && col0 > row0) {
        float* C = (float*)C0 + zoffC;
        float4 f = make_float4(-1e9f, -1e9f, -1e9f, -1e9f);
        #pragma unroll
        for (int i = 0; i < 16; i++) {
            int g = tid + i * 256;
            int r = g >> 5, c4 = (g & 31) << 2;
            *(float4*)(C + (size_t)(row0 + r) * ldc + col0 + c4) = f;
        }
        return;
    }

    int Keff = (CAUSAL == 2) ? min(K, row0 + 128) : K;
    const int nc = Keff >> 5;

    const uint32_t sb = smem_u32(smem);
    const int wm = (wid & 3) * 32;
    const int wn = (wid >> 2) * 64;
    const int lrow = lid & 15;
    const int lcol = (lid >> 4) << 3;

    float acc[2][8][4];
    #pragma unroll
    for (int mt = 0; mt < 2; mt++)
        #pragma unroll
        for (int nt = 0; nt < 8; nt++)
            #pragma unroll
            for (int r = 0; r < 4; r++) acc[mt][nt][r] = 0.f;

    // prologue: 3 stages in flight (always commit 3 groups)
    #pragma unroll
    for (int s = 0; s < 3; s++) {
        if (s < nc) load_stage_async(sb + s * STGB, Ah, Al, Bh, Bl, lda, ldb, row0, col0, s << 5);
        CP_COMMIT();
    }
    CP_WAIT2();
    __syncthreads();

    Frags fa, fb;
    ldfrags(fa, sb, 0, wm, wn, lrow, lcol);

    for (int c = 0; c < nc; c++) {
        uint32_t stg = sb + (c & 3) * STGB;
        ldfrags(fb, stg, 16, wm, wn, lrow, lcol);   // second half of this chunk
        mma_frags(fa, acc);                          // first half
        bool more = (c + 1 < nc);
        if (more) { CP_WAIT1(); }
        __syncthreads();
        if (c + 3 < nc)
            load_stage_async(sb + ((c + 3) & 3) * STGB, Ah, Al, Bh, Bl,
                             lda, ldb, row0, col0, (c + 3) << 5);
        CP_COMMIT();
        if (more) ldfrags(fa, sb + ((c + 1) & 3) * STGB, 0, wm, wn, lrow, lcol);
        mma_frags(fb, acc);                          // second half
    }

    // ---------------- epilogue ----------------
    #pragma unroll
    for (int mt = 0; mt < 2; mt++) {
        #pragma unroll
        for (int nt = 0; nt < 8; nt++) {
            int gr0 = row0 + wm + mt * 16 + (lid >> 2);
            int gc  = col0 + wn + nt * 8 + (lid & 3) * 2;
            #pragma unroll
            for (int half = 0; half < 2; half++) {
                int gr = gr0 + half * 8;
                float v0 = acc[mt][nt][2 * half]     * alpha;
                float v1 = acc[mt][nt][2 * half + 1] * alpha;
                if (bias) { v0 += bias[gc]; v1 += bias[gc + 1]; }
                if (CAUSAL == 1) {
                    const float* mp = Ms + (size_t)gr * ldm + gc;
                    v0 += mp[0]; v1 += mp[1];
                }
                if (EPI == 0) {
                    float* C = (float*)C0 + zoffC + (size_t)gr * ldc + gc;
                    *(float2*)C = make_float2(v0, v1);
                } else {
                    __nv_bfloat16* Ch = (__nv_bfloat16*)C0 + zoffC + (size_t)gr * ldc + gc;
                    __nv_bfloat16* Cl = (__nv_bfloat16*)C1 + zoffC + (size_t)gr * ldc + gc;
                    union { __nv_bfloat16 b[2]; uint32_t u; } H, L;
                    split1(v0, H.b[0], L.b[0]);
                    split1(v1, H.b[1], L.b[1]);
                    *(uint32_t*)Ch = H.u;
                    *(uint32_t*)Cl = L.u;
                }
            }
        }
    }
}

// ---------------- launch ----------------
extern "C" void kernel_launch(void* const* d_in, const int* in_sizes, int n_in,
                              void* d_out, int out_size) {
    const float* x      = (const float*)d_in[0];
    const float* mask   = (const float*)d_in[1];
    const float* Wqkv_w = (const float*)d_in[2];
    const float* Wqkv_b = (const float*)d_in[3];
    const float* out_w  = (const float*)d_in[4];
    const float* out_b  = (const float*)d_in[5];

    float* out  = (float*)d_out;
    float* kout = out  + (size_t)M1 * DIMC;
    float* vout = kout + (size_t)8 * SEQ * HDIM;

    float *qkv, *S;
    __nv_bfloat16 *xh,*xl,*wqh,*wql,*owh,*owl,*qh,*ql,*kh,*kl,*vth,*vtl,*ph,*pl,*vhh,*vhl;
    cudaGetSymbolAddress((void**)&qkv, g_qkv);
    cudaGetSymbolAddress((void**)&S,   g_s);
    cudaGetSymbolAddress((void**)&xh,  g_xh);  cudaGetSymbolAddress((void**)&xl,  g_xl);
    cudaGetSymbolAddress((void**)&wqh, g_wqh); cudaGetSymbolAddress((void**)&wql, g_wql);
    cudaGetSymbolAddress((void**)&owh, g_owh); cudaGetSymbolAddress((void**)&owl, g_owl);
    cudaGetSymbolAddress((void**)&qh,  g_qh);  cudaGetSymbolAddress((void**)&ql,  g_ql);
    cudaGetSymbolAddress((void**)&kh,  g_kh);  cudaGetSymbolAddress((void**)&kl,  g_kl);
    cudaGetSymbolAddress((void**)&vth, g_vth); cudaGetSymbolAddress((void**)&vtl, g_vtl);
    cudaGetSymbolAddress((void**)&ph,  g_ph);  cudaGetSymbolAddress((void**)&pl,  g_pl);
    cudaGetSymbolAddress((void**)&vhh, g_vhh); cudaGetSymbolAddress((void**)&vhl, g_vhl);

    cudaFuncSetAttribute(gemm_mma<0,0>, cudaFuncAttributeMaxDynamicSharedMemorySize, SMEM_MMA);
    cudaFuncSetAttribute(gemm_mma<1,0>, cudaFuncAttributeMaxDynamicSharedMemorySize, SMEM_MMA);
    cudaFuncSetAttribute(gemm_mma<2,1>, cudaFuncAttributeMaxDynamicSharedMemorySize, SMEM_MMA);

    // 1) RoPE tables
    rope_tab_kernel<<<SEQ, 512>>>();

    // 2) split inputs to bf16 hi/lo
    conv_split<<<(int)((size_t)M1*DIMC/1024),  256>>>(x, xh, xl);
    conv_split<<<(int)((size_t)QKVN*DIMC/1024),256>>>(Wqkv_w, wqh, wql);
    conv_split<<<(int)((size_t)DIMC*DIMC/1024),256>>>(out_w, owh, owl);

    // 3) QKV = x @ Wqkv^T + b   [8192 x 6144 x 2048]
    gemm_mma<0,0><<<dim3(QKVN/128, M1/128, 1), 256, SMEM_MMA>>>(
        xh, xl, wqh, wql, Wqkv_b, nullptr, qkv, nullptr,
        DIMC, DIMC, DIMC, QKVN, 0, 0, 0, 0, 0, 1, 1.0f);

    // 4) RoPE: roped q/k hi-lo, k/v fp32 -> d_out
    rope_apply<<<(8 * SEQ * 512) / 256, 256>>>(qkv, qh, ql, kh, kl, kout, vout);

    // 5) V transpose + split: Vt[b,h,d,l]
    vt_kernel<<<dim3(SEQ/32, HDIM/32, 8), dim3(32, 8)>>>(qkv, vth, vtl);

    // 6) S = (1/32) q @ k^T + mask  per head, causal fill
    gemm_mma<1,0><<<dim3(SEQ/128, SEQ/128, 8), 256, SMEM_MMA>>>(
        qh, ql, kh, kl, nullptr, mask, S, nullptr,
        HDIM, HDIM, HDIM, SEQ, SEQ,
        (long)SEQ*HDIM, (long)SEQ*HDIM, (long)SEQ*SEQ, 0, 1, 0.03125f);

    // 7) softmax + split P to bf16 hi/lo
    softmax_split<<<8 * SEQ, 256>>>(S, ph, pl);

    // 8) VH = P @ V (via Vt), causal K-limit; split output scattered to (B,L,D)
    gemm_mma<2,1><<<dim3(HDIM/128, SEQ/128, 8), 256, SMEM_MMA>>>(
        ph, pl, vth, vtl, nullptr, nullptr, vhh, vhl,
        SEQ, SEQ, SEQ, DIMC, 0,
        (long)SEQ*SEQ, (long)HDIM*SEQ, (long)SEQ*DIMC, (long)HDIM, NHEADS, 1.0f);

    // 9) out = VH @ out_w^T + out_b  [8192 x 2048 x 2048]
    gemm_mma<0,0><<<dim3(DIMC/128, M1/128, 1), 256, SMEM_MMA>>>(
        vhh, vhl, owh, owl, out_b, nullptr, out, nullptr,
        DIMC, DIMC, DIMC, DIMC, 0, 0, 0, 0, 0, 1, 1.0f);
}

// round 6
// speedup vs baseline: 2.7330x; 1.4639x over previous
#include <cuda_runtime.h>
#include <cuda_fp16.h>
#include <math.h>
#include <stdint.h>

// ---------------- problem constants ----------------
#define DIMC   2048
#define NHEADS 2
#define HDIM   1024
#define BATCH  4
#define SEQ    2048
#define M1     (BATCH*SEQ)   // 8192
#define QKVN   (3*DIMC)      // 6144

__device__ __forceinline__ uint32_t smem_u32(const void* p) {
    uint32_t a;
    asm("{ .reg .u64 t; cvta.to.shared.u64 t, %1; cvt.u32.u64 %0, t; }" : "=r"(a) : "l"(p));
    return a;
}
__device__ __forceinline__ void split1h(float v, __half& h, __half& l) {
    h = __float2half_rn(v);
    l = __float2half_rn(v - __half2float(h));
}

#define CP_ASYNC16(dst, src) \
    asm volatile("cp.async.cg.shared.global [%0], [%1], 16;" :: "r"(dst), "l"(src) : "memory")
#define CP_COMMIT() asm volatile("cp.async.commit_group;" ::: "memory")
#define CP_WAIT1()  asm volatile("cp.async.wait_group 1;" ::: "memory")
#define CP_WAIT0()  asm volatile("cp.async.wait_group 0;" ::: "memory")

#define LDMATRIX_X4(r0, r1, r2, r3, addr) \
    asm volatile("ldmatrix.sync.aligned.m8n8.x4.shared.b16 {%0,%1,%2,%3}, [%4];" \
        : "=r"(r0), "=r"(r1), "=r"(r2), "=r"(r3) : "r"(addr))

#define MMA_F16(c, a, b0, b1) \
    asm volatile("mma.sync.aligned.m16n8k16.row.col.f32.f16.f16.f32 " \
        "{%0,%1,%2,%3}, {%4,%5,%6,%7}, {%8,%9}, {%0,%1,%2,%3};" \
        : "+f"((c)[0]), "+f"((c)[1]), "+f"((c)[2]), "+f"((c)[3]) \
        : "r"((a)[0]), "r"((a)[1]), "r"((a)[2]), "r"((a)[3]), "r"(b0), "r"(b1))

// ---------------- scratch ----------------
__device__ float g_qkv[(size_t)M1 * QKVN];
__device__ float g_s  [(size_t)8 * SEQ * SEQ];
__device__ float g_ctab[SEQ * 512];
__device__ float g_stab[SEQ * 512];
__device__ __align__(128) __half g_xf [(size_t)M1*DIMC];
__device__ __align__(128) __half g_wqh[(size_t)QKVN*DIMC], g_wql[(size_t)QKVN*DIMC];
__device__ __align__(128) __half g_owh[(size_t)DIMC*DIMC], g_owl[(size_t)DIMC*DIMC];
__device__ __align__(128) __half g_qf [(size_t)8*SEQ*HDIM];
__device__ __align__(128) __half g_kh [(size_t)8*SEQ*HDIM], g_kl[(size_t)8*SEQ*HDIM];
__device__ __align__(128) __half g_vth[(size_t)8*HDIM*SEQ], g_vtl[(size_t)8*HDIM*SEQ];
__device__ __align__(128) __half g_pf [(size_t)8*SEQ*SEQ];
__device__ __align__(128) __half g_vhf[(size_t)M1*DIMC];

// ---------------- RoPE tables ----------------
__global__ void rope_tab_kernel() {
    int idx = blockIdx.x * blockDim.x + threadIdx.x;
    int d = idx & 511, l = idx >> 9;
    double inv = exp((double)(2 * d) * (-9.210340371976184 / 1024.0));
    double th  = (double)l * inv;
    g_ctab[idx] = (float)cos(th);
    g_stab[idx] = (float)sin(th);
}

// ---------------- fp32 -> fp16 single ----------------
__global__ void conv_h(const float* __restrict__ in, __half* __restrict__ o) {
    int i = blockIdx.x * 256 + threadIdx.x;
    float4 v = ((const float4*)in)[i];
    union { __half b[4]; uint2 u; } H;
    H.b[0] = __float2half_rn(v.x); H.b[1] = __float2half_rn(v.y);
    H.b[2] = __float2half_rn(v.z); H.b[3] = __float2half_rn(v.w);
    ((uint2*)o)[i] = H.u;
}

// ---------------- fp32 -> fp16 hi/lo split ----------------
__global__ void conv_split_h(const float* __restrict__ in,
                             __half* __restrict__ oh, __half* __restrict__ ol) {
    int i = blockIdx.x * 256 + threadIdx.x;
    float4 v = ((const float4*)in)[i];
    union { __half b[4]; uint2 u; } H, L;
    split1h(v.x, H.b[0], L.b[0]); split1h(v.y, H.b[1], L.b[1]);
    split1h(v.z, H.b[2], L.b[2]); split1h(v.w, H.b[3], L.b[3]);
    ((uint2*)oh)[i] = H.u;
    ((uint2*)ol)[i] = L.u;
}

// ---------------- RoPE apply ----------------
__global__ void rope_apply(const float* __restrict__ qkv,
                           __half* __restrict__ qf,
                           __half* __restrict__ kh, __half* __restrict__ kl,
                           float* __restrict__ kout, float* __restrict__ vout) {
    int idx = blockIdx.x * blockDim.x + threadIdx.x;
    int d = idx & 511;
    int l = (idx >> 9) & (SEQ - 1);
    int h = (idx >> 20) & 1;
    int b = idx >> 21;
    int ti = (l << 9) + d;
    float c = g_ctab[ti], s = g_stab[ti];
    const float* row = qkv + (size_t)(b * SEQ + l) * QKVN;
    int off = h * HDIM + d;
    float q1 = row[off],          q2 = row[off + 512];
    float k1 = row[DIMC + off],   k2 = row[DIMC + off + 512];
    float v1 = row[2*DIMC + off], v2 = row[2*DIMC + off + 512];
    size_t o = (size_t)((b * NHEADS + h) * SEQ + l) * HDIM + d;
    float rq1 = q1*c - q2*s, rq2 = q1*s + q2*c;
    float rk1 = k1*c - k2*s, rk2 = k1*s + k2*c;
    qf[o]       = __float2half_rn(rq1);
    qf[o + 512] = __float2half_rn(rq2);
    split1h(rk1, kh[o],       kl[o]);
    split1h(rk2, kh[o + 512], kl[o + 512]);
    kout[o] = rk1; kout[o + 512] = rk2;
    vout[o] = v1;  vout[o + 512] = v2;
}

// ---------------- V transpose + split: qkv(v) -> Vt[b,h,d,l] hi/lo ----------------
__global__ void vt_kernel(const float* __restrict__ qkv,
                          __half* __restrict__ vth, __half* __restrict__ vtl) {
    __shared__ float tile[32][33];
    int z = blockIdx.z;
    int b = z >> 1, h = z & 1;
    int l0 = blockIdx.x * 32, d0 = blockIdx.y * 32;
    int tx = threadIdx.x, ty = threadIdx.y;
    #pragma unroll
    for (int j = 0; j < 32; j += 8) {
        int l = l0 + ty + j, d = d0 + tx;
        tile[ty + j][tx] = qkv[(size_t)(b * SEQ + l) * QKVN + 2*DIMC + h*HDIM + d];
    }
    __syncthreads();
    #pragma unroll
    for (int j = 0; j < 32; j += 8) {
        int d = d0 + ty + j, l = l0 + tx;
        float v = tile[tx][ty + j];
        size_t o = ((size_t)z * HDIM + d) * SEQ + l;
        split1h(v, vth[o], vtl[o]);
    }
}

// ---------------- softmax -> fp16 P ----------------
__global__ void softmax_h(const float* __restrict__ S, __half* __restrict__ P) {
    size_t row = blockIdx.x;
    const float* p = S + row * (size_t)SEQ;
    int t = threadIdx.x;
    float v[8];
    float4 v0 = *(const float4*)(p + t * 8);
    float4 v1 = *(const float4*)(p + t * 8 + 4);
    v[0]=v0.x; v[1]=v0.y; v[2]=v0.z; v[3]=v0.w;
    v[4]=v1.x; v[5]=v1.y; v[6]=v1.z; v[7]=v1.w;
    float m = v[0];
    #pragma unroll
    for (int j = 1; j < 8; j++) m = fmaxf(m, v[j]);
    __shared__ float red[256];
    red[t] = m; __syncthreads();
    #pragma unroll
    for (int s = 128; s > 0; s >>= 1) { if (t < s) red[t] = fmaxf(red[t], red[t + s]); __syncthreads(); }
    float mx = red[0]; __syncthreads();
    float sum = 0.f;
    #pragma unroll
    for (int j = 0; j < 8; j++) { v[j] = expf(v[j] - mx); sum += v[j]; }
    red[t] = sum; __syncthreads();
    #pragma unroll
    for (int s = 128; s > 0; s >>= 1) { if (t < s) red[t] += red[t + s]; __syncthreads(); }
    float inv = 1.0f / red[0];
    union { __half b[8]; uint4 u; } H;
    #pragma unroll
    for (int j = 0; j < 8; j++) H.b[j] = __float2half_rn(v[j] * inv);
    *(uint4*)(P + row * SEQ + t * 8) = H.u;
}

// ---------------- warp-MMA fp16 2-pass GEMM ----------------
// C = alpha*(A@(Bh+Bl)^T) (+bias) (+mask). A=[M,K] K-major fp16, B=[N,K] K-major fp16 hi/lo.
// Block 128x128x32, 8 warps (4x2), warp tile 32x64, m16n8k16 fp16, 3-stage cp.async.
// CAUSAL: 0 none; 1 fill above-diag tiles with -1e9; 2 K-limit to row0+128.
// EPI: 0 -> fp32 C0; 1 -> fp16 C0.
#define KPAD   40
#define MATB   (128 * KPAD * 2)    // 10240 B per matrix tile
#define STGB   (3 * MATB)          // 30720 B per stage (A, Bh, Bl)
#define NSTG   3
#define SMEM_MMA (NSTG * STGB)

__device__ __forceinline__ void load_stage_async(uint32_t sbase,
    const __half* A, const __half* Bh, const __half* Bl,
    int lda, int ldb, int row0, int col0, int k0)
{
    const int t = threadIdx.x;
    const __half* srcs[3] = {A, Bh, Bl};
    #pragma unroll
    for (int i = 0; i < 6; i++) {
        int s = t + i * 256;
        int m   = s >> 9;           // matrix 0..2
        int idx = s & 511;
        int row = idx >> 2;
        int c16 = idx & 3;
        int ld  = (m < 1) ? lda : ldb;
        int r0  = (m < 1) ? row0 : col0;
        const __half* src = srcs[m] + (size_t)(r0 + row) * ld + k0 + c16 * 8;
        uint32_t dst = sbase + m * MATB + row * (KPAD * 2) + c16 * 16;
        CP_ASYNC16(dst, src);
    }
}

template<int CAUSAL, int EPI>
__global__ void __launch_bounds__(256, 1) gemm_mma(
    const __half* __restrict__ A, const __half* __restrict__ Bh, const __half* __restrict__ Bl,
    const float* __restrict__ bias, const float* __restrict__ Ms,
    void* __restrict__ C0,
    int K, int lda, int ldb, int ldc, int ldm,
    long sA, long sB, long sCo, long sCi, int zdiv, float alpha)
{
    extern __shared__ char smem[];
    const int tid = threadIdx.x;
    const int wid = tid >> 5;
    const int lid = tid & 31;
    const int row0 = blockIdx.y * 128;
    const int col0 = blockIdx.x * 128;
    const int bz = blockIdx.z;

    const size_t zoffC = (size_t)(bz / zdiv) * sCo + (size_t)(bz % zdiv) * sCi;
    A  += (size_t)bz * sA;
    Bh += (size_t)bz * sB;
    Bl += (size_t)bz * sB;

    if (CAUSAL == 1 && col0 > row0) {
        float* C = (float*)C0 + zoffC;
        float4 f = make_float4(-1e9f, -1e9f, -1e9f, -1e9f);
        #pragma unroll
        for (int i = 0; i < 16; i++) {
            int g = tid + i * 256;
            int r = g >> 5, c4 = (g & 31) << 2;
            *(float4*)(C + (size_t)(row0 + r) * ldc + col0 + c4) = f;
        }
        return;
    }

    int Keff = (CAUSAL == 2) ? min(K, row0 + 128) : K;
    const int nc = Keff >> 5;

    const uint32_t sb = smem_u32(smem);
    const int wm = (wid & 3) * 32;
    const int wn = (wid >> 2) * 64;
    const int lrow = lid & 15;
    const int lcol = (lid >> 4) << 3;

    float acc[2][8][4];
    #pragma unroll
    for (int mt = 0; mt < 2; mt++)
        #pragma unroll
        for (int nt = 0; nt < 8; nt++)
            #pragma unroll
            for (int r = 0; r < 4; r++) acc[mt][nt][r] = 0.f;

    load_stage_async(sb, A, Bh, Bl, lda, ldb, row0, col0, 0);
    CP_COMMIT();
    if (nc > 1) load_stage_async(sb + STGB, A, Bh, Bl, lda, ldb, row0, col0, 32);
    CP_COMMIT();

    for (int c = 0; c < nc; c++) {
        if (c + 1 < nc) { CP_WAIT1(); } else { CP_WAIT0(); }
        __syncthreads();
        if (c + 2 < nc) {
            load_stage_async(sb + ((c + 2) % NSTG) * STGB, A, Bh, Bl,
                             lda, ldb, row0, col0, (c + 2) << 5);
            CP_COMMIT();
        }

        uint32_t stg = sb + (c % NSTG) * STGB;
        #pragma unroll
        for (int kk = 0; kk < 32; kk += 16) {
            uint32_t af[2][4], bHf[4][4], bLf[4][4];
            #pragma unroll
            for (int mt = 0; mt < 2; mt++) {
                uint32_t ra = stg + ((wm + mt * 16 + lrow) * KPAD + kk + lcol) * 2;
                LDMATRIX_X4(af[mt][0], af[mt][1], af[mt][2], af[mt][3], ra);
            }
            #pragma unroll
            for (int g = 0; g < 4; g++) {
                uint32_t rb = stg + MATB + ((wn + g * 16 + lrow) * KPAD + kk + lcol) * 2;
                LDMATRIX_X4(bHf[g][0], bHf[g][1], bHf[g][2], bHf[g][3], rb);
                LDMATRIX_X4(bLf[g][0], bLf[g][1], bLf[g][2], bLf[g][3], rb + MATB);
            }
            #pragma unroll
            for (int mt = 0; mt < 2; mt++)
                #pragma unroll
                for (int nt = 0; nt < 8; nt++) {
                    int g = nt >> 1, o = nt & 1;
                    MMA_F16(acc[mt][nt], af[mt], bHf[g][o], bHf[g][o + 2]);
                    MMA_F16(acc[mt][nt], af[mt], bLf[g][o], bLf[g][o + 2]);
                }
        }
        __syncthreads();
    }

    // ---------------- epilogue ----------------
    #pragma unroll
    for (int mt = 0; mt < 2; mt++) {
        #pragma unroll
        for (int nt = 0; nt < 8; nt++) {
            int gr0 = row0 + wm + mt * 16 + (lid >> 2);
            int gc  = col0 + wn + nt * 8 + (lid & 3) * 2;
            #pragma unroll
            for (int half = 0; half < 2; half++) {
                int gr = gr0 + half * 8;
                float v0 = acc[mt][nt][2 * half]     * alpha;
                float v1 = acc[mt][nt][2 * half + 1] * alpha;
                if (bias) { v0 += bias[gc]; v1 += bias[gc + 1]; }
                if (CAUSAL == 1) {
                    const float* mp = Ms + (size_t)gr * ldm + gc;
                    v0 += mp[0]; v1 += mp[1];
                }
                if (EPI == 0) {
                    float* C = (float*)C0 + zoffC + (size_t)gr * ldc + gc;
                    *(float2*)C = make_float2(v0, v1);
                } else {
                    __half* C = (__half*)C0 + zoffC + (size_t)gr * ldc + gc;
                    union { __half b[2]; uint32_t u; } H;
                    H.b[0] = __float2half_rn(v0);
                    H.b[1] = __float2half_rn(v1);
                    *(uint32_t*)C = H.u;
                }
            }
        }
    }
}

// ---------------- launch ----------------
extern "C" void kernel_launch(void* const* d_in, const int* in_sizes, int n_in,
                              void* d_out, int out_size) {
    const float* x      = (const float*)d_in[0];
    const float* mask   = (const float*)d_in[1];
    const float* Wqkv_w = (const float*)d_in[2];
    const float* Wqkv_b = (const float*)d_in[3];
    const float* out_w  = (const float*)d_in[4];
    const float* out_b  = (const float*)d_in[5];

    float* out  = (float*)d_out;
    float* kout = out  + (size_t)M1 * DIMC;
    float* vout = kout + (size_t)8 * SEQ * HDIM;

    float *qkv, *S;
    __half *xf,*wqh,*wql,*owh,*owl,*qf,*kh,*kl,*vth,*vtl,*pf,*vhf;
    cudaGetSymbolAddress((void**)&qkv, g_qkv);
    cudaGetSymbolAddress((void**)&S,   g_s);
    cudaGetSymbolAddress((void**)&xf,  g_xf);
    cudaGetSymbolAddress((void**)&wqh, g_wqh); cudaGetSymbolAddress((void**)&wql, g_wql);
    cudaGetSymbolAddress((void**)&owh, g_owh); cudaGetSymbolAddress((void**)&owl, g_owl);
    cudaGetSymbolAddress((void**)&qf,  g_qf);
    cudaGetSymbolAddress((void**)&kh,  g_kh);  cudaGetSymbolAddress((void**)&kl,  g_kl);
    cudaGetSymbolAddress((void**)&vth, g_vth); cudaGetSymbolAddress((void**)&vtl, g_vtl);
    cudaGetSymbolAddress((void**)&pf,  g_pf);
    cudaGetSymbolAddress((void**)&vhf, g_vhf);

    cudaFuncSetAttribute(gemm_mma<0,0>, cudaFuncAttributeMaxDynamicSharedMemorySize, SMEM_MMA);
    cudaFuncSetAttribute(gemm_mma<1,0>, cudaFuncAttributeMaxDynamicSharedMemorySize, SMEM_MMA);
    cudaFuncSetAttribute(gemm_mma<2,1>, cudaFuncAttributeMaxDynamicSharedMemorySize, SMEM_MMA);

    // 1) RoPE tables
    rope_tab_kernel<<<SEQ, 512>>>();

    // 2) convert inputs: x -> fp16; weights -> fp16 hi/lo
    conv_h      <<<(int)((size_t)M1*DIMC/1024),  256>>>(x, xf);
    conv_split_h<<<(int)((size_t)QKVN*DIMC/1024),256>>>(Wqkv_w, wqh, wql);
    conv_split_h<<<(int)((size_t)DIMC*DIMC/1024),256>>>(out_w, owh, owl);

    // 3) QKV = x @ Wqkv^T + b   [8192 x 6144 x 2048]
    gemm_mma<0,0><<<dim3(QKVN/128, M1/128, 1), 256, SMEM_MMA>>>(
        xf, wqh, wql, Wqkv_b, nullptr, qkv,
        DIMC, DIMC, DIMC, QKVN, 0, 0, 0, 0, 0, 1, 1.0f);

    // 4) RoPE: q fp16, k hi/lo fp16, k/v fp32 -> d_out
    rope_apply<<<(8 * SEQ * 512) / 256, 256>>>(qkv, qf, kh, kl, kout, vout);

    // 5) V transpose + split: Vt[b,h,d,l] hi/lo
    vt_kernel<<<dim3(SEQ/32, HDIM/32, 8), dim3(32, 8)>>>(qkv, vth, vtl);

    // 6) S = (1/32) q @ k^T + mask  per head, causal fill
    gemm_mma<1,0><<<dim3(SEQ/128, SEQ/128, 8), 256, SMEM_MMA>>>(
        qf, kh, kl, nullptr, mask, S,
        HDIM, HDIM, HDIM, SEQ, SEQ,
        (long)SEQ*HDIM, (long)SEQ*HDIM, (long)SEQ*SEQ, 0, 1, 0.03125f);

    // 7) softmax -> fp16 P
    softmax_h<<<8 * SEQ, 256>>>(S, pf);

    // 8) VH = P @ V (via Vt hi/lo), causal K-limit; fp16 out scattered to (B,L,D)
    gemm_mma<2,1><<<dim3(HDIM/128, SEQ/128, 8), 256, SMEM_MMA>>>(
        pf, vth, vtl, nullptr, nullptr, vhf,
        SEQ, SEQ, SEQ, DIMC, 0,
        (long)SEQ*SEQ, (long)HDIM*SEQ, (long)SEQ*DIMC, (long)HDIM, NHEADS, 1.0f);

    // 9) out = VH @ out_w^T + out_b  [8192 x 2048 x 2048]
    gemm_mma<0,0><<<dim3(DIMC/128, M1/128, 1), 256, SMEM_MMA>>>(
        vhf, owh, owl, out_b, nullptr, out,
        DIMC, DIMC, DIMC, DIMC, 0, 0, 0, 0, 0, 1, 1.0f);
}

// round 7
// speedup vs baseline: 2.7552x; 1.0081x over previous
#include <cuda_runtime.h>
#include <cuda_fp16.h>
#include <math.h>
#include <stdint.h>

// ---------------- problem constants ----------------
#define DIMC   2048
#define NHEADS 2
#define HDIM   1024
#define BATCH  4
#define SEQ    2048
#define M1     (BATCH*SEQ)   // 8192
#define QKVN   (3*DIMC)      // 6144

__device__ __forceinline__ uint32_t smem_u32(const void* p) {
    uint32_t a;
    asm("{ .reg .u64 t; cvta.to.shared.u64 t, %1; cvt.u32.u64 %0, t; }" : "=r"(a) : "l"(p));
    return a;
}
__device__ __forceinline__ void split1h(float v, __half& h, __half& l) {
    h = __float2half_rn(v);
    l = __float2half_rn(v - __half2float(h));
}

#define CP_ASYNC16(dst, src) \
    asm volatile("cp.async.cg.shared.global [%0], [%1], 16;" :: "r"(dst), "l"(src) : "memory")
#define CP_COMMIT() asm volatile("cp.async.commit_group;" ::: "memory")
#define CP_WAIT1()  asm volatile("cp.async.wait_group 1;" ::: "memory")
#define CP_WAIT0()  asm volatile("cp.async.wait_group 0;" ::: "memory")

#define LDMATRIX_X4(r0, r1, r2, r3, addr) \
    asm volatile("ldmatrix.sync.aligned.m8n8.x4.shared.b16 {%0,%1,%2,%3}, [%4];" \
        : "=r"(r0), "=r"(r1), "=r"(r2), "=r"(r3) : "r"(addr))

// fp16 MMA, fp32 accumulator (main pass)
#define MMA_F16(c, a, b0, b1) \
    asm volatile("mma.sync.aligned.m16n8k16.row.col.f32.f16.f16.f32 " \
        "{%0,%1,%2,%3}, {%4,%5,%6,%7}, {%8,%9}, {%0,%1,%2,%3};" \
        : "+f"((c)[0]), "+f"((c)[1]), "+f"((c)[2]), "+f"((c)[3]) \
        : "r"((a)[0]), "r"((a)[1]), "r"((a)[2]), "r"((a)[3]), "r"(b0), "r"(b1))

// fp16 MMA, fp16 accumulator (low-correction pass)
#define MMA_F16A16(ch, a, b0, b1) \
    asm volatile("mma.sync.aligned.m16n8k16.row.col.f16.f16.f16.f16 " \
        "{%0,%1}, {%2,%3,%4,%5}, {%6,%7}, {%0,%1};" \
        : "+r"((ch)[0]), "+r"((ch)[1]) \
        : "r"((a)[0]), "r"((a)[1]), "r"((a)[2]), "r"((a)[3]), "r"(b0), "r"(b1))

// ---------------- scratch ----------------
__device__ float g_qkv[(size_t)M1 * QKVN];
__device__ float g_s  [(size_t)8 * SEQ * SEQ];
__device__ float g_ctab[SEQ * 512];
__device__ float g_stab[SEQ * 512];
__device__ __align__(128) __half g_xf [(size_t)M1*DIMC];
__device__ __align__(128) __half g_wqh[(size_t)QKVN*DIMC], g_wql[(size_t)QKVN*DIMC];
__device__ __align__(128) __half g_owh[(size_t)DIMC*DIMC], g_owl[(size_t)DIMC*DIMC];
__device__ __align__(128) __half g_qf [(size_t)8*SEQ*HDIM];
__device__ __align__(128) __half g_kh [(size_t)8*SEQ*HDIM], g_kl[(size_t)8*SEQ*HDIM];
__device__ __align__(128) __half g_vth[(size_t)8*HDIM*SEQ], g_vtl[(size_t)8*HDIM*SEQ];
__device__ __align__(128) __half g_pf [(size_t)8*SEQ*SEQ];
__device__ __align__(128) __half g_vhf[(size_t)M1*DIMC];

// ---------------- RoPE tables ----------------
__global__ void rope_tab_kernel() {
    int idx = blockIdx.x * blockDim.x + threadIdx.x;
    int d = idx & 511, l = idx >> 9;
    double inv = exp((double)(2 * d) * (-9.210340371976184 / 1024.0));
    double th  = (double)l * inv;
    g_ctab[idx] = (float)cos(th);
    g_stab[idx] = (float)sin(th);
}

// ---------------- fp32 -> fp16 single ----------------
__global__ void conv_h(const float* __restrict__ in, __half* __restrict__ o) {
    int i = blockIdx.x * 256 + threadIdx.x;
    float4 v = ((const float4*)in)[i];
    union { __half b[4]; uint2 u; } H;
    H.b[0] = __float2half_rn(v.x); H.b[1] = __float2half_rn(v.y);
    H.b[2] = __float2half_rn(v.z); H.b[3] = __float2half_rn(v.w);
    ((uint2*)o)[i] = H.u;
}

// ---------------- fp32 -> fp16 hi/lo split ----------------
__global__ void conv_split_h(const float* __restrict__ in,
                             __half* __restrict__ oh, __half* __restrict__ ol) {
    int i = blockIdx.x * 256 + threadIdx.x;
    float4 v = ((const float4*)in)[i];
    union { __half b[4]; uint2 u; } H, L;
    split1h(v.x, H.b[0], L.b[0]); split1h(v.y, H.b[1], L.b[1]);
    split1h(v.z, H.b[2], L.b[2]); split1h(v.w, H.b[3], L.b[3]);
    ((uint2*)oh)[i] = H.u;
    ((uint2*)ol)[i] = L.u;
}

// ---------------- RoPE apply ----------------
__global__ void rope_apply(const float* __restrict__ qkv,
                           __half* __restrict__ qf,
                           __half* __restrict__ kh, __half* __restrict__ kl,
                           float* __restrict__ kout, float* __restrict__ vout) {
    int idx = blockIdx.x * blockDim.x + threadIdx.x;
    int d = idx & 511;
    int l = (idx >> 9) & (SEQ - 1);
    int h = (idx >> 20) & 1;
    int b = idx >> 21;
    int ti = (l << 9) + d;
    float c = g_ctab[ti], s = g_stab[ti];
    const float* row = qkv + (size_t)(b * SEQ + l) * QKVN;
    int off = h * HDIM + d;
    float q1 = row[off],          q2 = row[off + 512];
    float k1 = row[DIMC + off],   k2 = row[DIMC + off + 512];
    float v1 = row[2*DIMC + off], v2 = row[2*DIMC + off + 512];
    size_t o = (size_t)((b * NHEADS + h) * SEQ + l) * HDIM + d;
    float rq1 = q1*c - q2*s, rq2 = q1*s + q2*c;
    float rk1 = k1*c - k2*s, rk2 = k1*s + k2*c;
    qf[o]       = __float2half_rn(rq1);
    qf[o + 512] = __float2half_rn(rq2);
    split1h(rk1, kh[o],       kl[o]);
    split1h(rk2, kh[o + 512], kl[o + 512]);
    kout[o] = rk1; kout[o + 512] = rk2;
    vout[o] = v1;  vout[o + 512] = v2;
}

// ---------------- V transpose + split: qkv(v) -> Vt[b,h,d,l] hi/lo ----------------
__global__ void vt_kernel(const float* __restrict__ qkv,
                          __half* __restrict__ vth, __half* __restrict__ vtl) {
    __shared__ float tile[32][33];
    int z = blockIdx.z;
    int b = z >> 1, h = z & 1;
    int l0 = blockIdx.x * 32, d0 = blockIdx.y * 32;
    int tx = threadIdx.x, ty = threadIdx.y;
    #pragma unroll
    for (int j = 0; j < 32; j += 8) {
        int l = l0 + ty + j, d = d0 + tx;
        tile[ty + j][tx] = qkv[(size_t)(b * SEQ + l) * QKVN + 2*DIMC + h*HDIM + d];
    }
    __syncthreads();
    #pragma unroll
    for (int j = 0; j < 32; j += 8) {
        int d = d0 + ty + j, l = l0 + tx;
        float v = tile[tx][ty + j];
        size_t o = ((size_t)z * HDIM + d) * SEQ + l;
        split1h(v, vth[o], vtl[o]);
    }
}

// ---------------- causal softmax -> fp16 P ----------------
// Row l: valid cols 0..l. Cols (l, (l|127)] written as exact 0 (PV K-limit
// reads that far); beyond never read. S above-diag tiles are never written.
__global__ void softmax_h(const float* __restrict__ S, __half* __restrict__ P) {
    int row = blockIdx.x;
    int l = row & (SEQ - 1);
    const float* p = S + (size_t)row * SEQ;
    int t = threadIdx.x;
    int nproc = (l | 127) + 1;
    bool act = (t * 8) < nproc;

    float v[8];
    float m = -1e30f;
    if (act) {
        float4 v0 = *(const float4*)(p + t * 8);
        float4 v1 = *(const float4*)(p + t * 8 + 4);
        v[0]=v0.x; v[1]=v0.y; v[2]=v0.z; v[3]=v0.w;
        v[4]=v1.x; v[5]=v1.y; v[6]=v1.z; v[7]=v1.w;
        #pragma unroll
        for (int j = 0; j < 8; j++)
            if (t * 8 + j <= l) m = fmaxf(m, v[j]);
    }
    __shared__ float red[256];
    red[t] = m; __syncthreads();
    #pragma unroll
    for (int s = 128; s > 0; s >>= 1) { if (t < s) red[t] = fmaxf(red[t], red[t + s]); __syncthreads(); }
    float mx = red[0]; __syncthreads();

    float sum = 0.f;
    if (act) {
        #pragma unroll
        for (int j = 0; j < 8; j++) {
            v[j] = (t * 8 + j <= l) ? __expf(v[j] - mx) : 0.f;
            sum += v[j];
        }
    }
    red[t] = sum; __syncthreads();
    #pragma unroll
    for (int s = 128; s > 0; s >>= 1) { if (t < s) red[t] += red[t + s]; __syncthreads(); }
    float inv = 1.0f / red[0];

    if (act) {
        union { __half b[8]; uint4 u; } H;
        #pragma unroll
        for (int j = 0; j < 8; j++) H.b[j] = __float2half_rn(v[j] * inv);
        *(uint4*)(P + (size_t)row * SEQ + t * 8) = H.u;
    }
}

// ---------------- warp-MMA fp16 GEMM: main pass f32-acc, low pass f16-acc ----------------
// C = alpha*(A@(Bh+Bl)^T) (+bias). A=[M,K] K-major fp16, B=[N,K] K-major fp16 hi/lo.
// Block 128x128x32, 8 warps (4x2), warp tile 32x64, 3-stage cp.async.
// CAUSAL: 0 none; 1 scores: skip tiles above diag, index-mask diag tiles; 2 K-limit row0+128.
// EPI: 0 -> fp32 C0; 1 -> fp16 C0.
#define KPAD   40
#define MATB   (128 * KPAD * 2)
#define STGB   (3 * MATB)
#define NSTG   3
#define SMEM_MMA (NSTG * STGB)

__device__ __forceinline__ void load_stage_async(uint32_t sbase,
    const __half* A, const __half* Bh, const __half* Bl,
    int lda, int ldb, int row0, int col0, int k0)
{
    const int t = threadIdx.x;
    const __half* srcs[3] = {A, Bh, Bl};
    #pragma unroll
    for (int i = 0; i < 6; i++) {
        int s = t + i * 256;
        int m   = s >> 9;
        int idx = s & 511;
        int row = idx >> 2;
        int c16 = idx & 3;
        int ld  = (m < 1) ? lda : ldb;
        int r0  = (m < 1) ? row0 : col0;
        const __half* src = srcs[m] + (size_t)(r0 + row) * ld + k0 + c16 * 8;
        uint32_t dst = sbase + m * MATB + row * (KPAD * 2) + c16 * 16;
        CP_ASYNC16(dst, src);
    }
}

template<int CAUSAL, int EPI>
__global__ void __launch_bounds__(256, 1) gemm_mma(
    const __half* __restrict__ A, const __half* __restrict__ Bh, const __half* __restrict__ Bl,
    const float* __restrict__ bias,
    void* __restrict__ C0,
    int K, int lda, int ldb, int ldc,
    long sA, long sB, long sCo, long sCi, int zdiv, float alpha)
{
    extern __shared__ char smem[];
    const int tid = threadIdx.x;
    const int wid = tid >> 5;
    const int lid = tid & 31;
    const int row0 = blockIdx.y * 128;
    const int col0 = blockIdx.x * 128;
    const int bz = blockIdx.z;

    if (CAUSAL == 1 && col0 > row0) return;   // never written; softmax skips region

    const size_t zoffC = (size_t)(bz / zdiv) * sCo + (size_t)(bz % zdiv) * sCi;
    A  += (size_t)bz * sA;
    Bh += (size_t)bz * sB;
    Bl += (size_t)bz * sB;

    int Keff = (CAUSAL == 2) ? min(K, row0 + 128) : K;
    const int nc = Keff >> 5;

    const uint32_t sb = smem_u32(smem);
    const int wm = (wid & 3) * 32;
    const int wn = (wid >> 2) * 64;
    const int lrow = lid & 15;
    const int lcol = (lid >> 4) << 3;

    float acc[2][8][4];
    uint32_t accl[2][8][2];
    #pragma unroll
    for (int mt = 0; mt < 2; mt++)
        #pragma unroll
        for (int nt = 0; nt < 8; nt++) {
            #pragma unroll
            for (int r = 0; r < 4; r++) acc[mt][nt][r] = 0.f;
            accl[mt][nt][0] = 0u; accl[mt][nt][1] = 0u;
        }

    load_stage_async(sb, A, Bh, Bl, lda, ldb, row0, col0, 0);
    CP_COMMIT();
    if (nc > 1) load_stage_async(sb + STGB, A, Bh, Bl, lda, ldb, row0, col0, 32);
    CP_COMMIT();

    for (int c = 0; c < nc; c++) {
        if (c + 1 < nc) { CP_WAIT1(); } else { CP_WAIT0(); }
        __syncthreads();
        if (c + 2 < nc) {
            load_stage_async(sb + ((c + 2) % NSTG) * STGB, A, Bh, Bl,
                             lda, ldb, row0, col0, (c + 2) << 5);
            CP_COMMIT();
        }

        uint32_t stg = sb + (c % NSTG) * STGB;
        #pragma unroll
        for (int kk = 0; kk < 32; kk += 16) {
            uint32_t af[2][4], bHf[4][4], bLf[4][4];
            #pragma unroll
            for (int mt = 0; mt < 2; mt++) {
                uint32_t ra = stg + ((wm + mt * 16 + lrow) * KPAD + kk + lcol) * 2;
                LDMATRIX_X4(af[mt][0], af[mt][1], af[mt][2], af[mt][3], ra);
            }
            #pragma unroll
            for (int g = 0; g < 4; g++) {
                uint32_t rb = stg + MATB + ((wn + g * 16 + lrow) * KPAD + kk + lcol) * 2;
                LDMATRIX_X4(bHf[g][0], bHf[g][1], bHf[g][2], bHf[g][3], rb);
                LDMATRIX_X4(bLf[g][0], bLf[g][1], bLf[g][2], bLf[g][3], rb + MATB);
            }
            #pragma unroll
            for (int mt = 0; mt < 2; mt++)
                #pragma unroll
                for (int nt = 0; nt < 8; nt++) {
                    int g = nt >> 1, o = nt & 1;
                    MMA_F16   (acc[mt][nt],  af[mt], bHf[g][o], bHf[g][o + 2]);
                    MMA_F16A16(accl[mt][nt], af[mt], bLf[g][o], bLf[g][o + 2]);
                }
        }
        __syncthreads();
    }

    // ---------------- epilogue (merge f16-acc low pass) ----------------
    #pragma unroll
    for (int mt = 0; mt < 2; mt++) {
        #pragma unroll
        for (int nt = 0; nt < 8; nt++) {
            int gr0 = row0 + wm + mt * 16 + (lid >> 2);
            int gc  = col0 + wn + nt * 8 + (lid & 3) * 2;
            float2 lo01 = __half22float2(*(__half2*)&accl[mt][nt][0]);
            float2 lo23 = __half22float2(*(__half2*)&accl[mt][nt][1]);
            #pragma unroll
            for (int half = 0; half < 2; half++) {
                int gr = gr0 + half * 8;
                float l0 = half ? lo23.x : lo01.x;
                float l1 = half ? lo23.y : lo01.y;
                float v0 = (acc[mt][nt][2 * half]     + l0) * alpha;
                float v1 = (acc[mt][nt][2 * half + 1] + l1) * alpha;
                if (bias) { v0 += bias[gc]; v1 += bias[gc + 1]; }
                if (CAUSAL == 1 && row0 == col0) {   // diagonal tile: index mask
                    if (gc     > gr) v0 = -1e9f;
                    if (gc + 1 > gr) v1 = -1e9f;
                }
                if (EPI == 0) {
                    float* C = (float*)C0 + zoffC + (size_t)gr * ldc + gc;
                    *(float2*)C = make_float2(v0, v1);
                } else {
                    __half* C = (__half*)C0 + zoffC + (size_t)gr * ldc + gc;
                    union { __half b[2]; uint32_t u; } H;
                    H.b[0] = __float2half_rn(v0);
                    H.b[1] = __float2half_rn(v1);
                    *(uint32_t*)C = H.u;
                }
            }
        }
    }
}

// ---------------- launch ----------------
extern "C" void kernel_launch(void* const* d_in, const int* in_sizes, int n_in,
                              void* d_out, int out_size) {
    const float* x      = (const float*)d_in[0];
    const float* Wqkv_w = (const float*)d_in[2];
    const float* Wqkv_b = (const float*)d_in[3];
    const float* out_w  = (const float*)d_in[4];
    const float* out_b  = (const float*)d_in[5];

    float* out  = (float*)d_out;
    float* kout = out  + (size_t)M1 * DIMC;
    float* vout = kout + (size_t)8 * SEQ * HDIM;

    float *qkv, *S;
    __half *xf,*wqh,*wql,*owh,*owl,*qf,*kh,*kl,*vth,*vtl,*pf,*vhf;
    cudaGetSymbolAddress((void**)&qkv, g_qkv);
    cudaGetSymbolAddress((void**)&S,   g_s);
    cudaGetSymbolAddress((void**)&xf,  g_xf);
    cudaGetSymbolAddress((void**)&wqh, g_wqh); cudaGetSymbolAddress((void**)&wql, g_wql);
    cudaGetSymbolAddress((void**)&owh, g_owh); cudaGetSymbolAddress((void**)&owl, g_owl);
    cudaGetSymbolAddress((void**)&qf,  g_qf);
    cudaGetSymbolAddress((void**)&kh,  g_kh);  cudaGetSymbolAddress((void**)&kl,  g_kl);
    cudaGetSymbolAddress((void**)&vth, g_vth); cudaGetSymbolAddress((void**)&vtl, g_vtl);
    cudaGetSymbolAddress((void**)&pf,  g_pf);
    cudaGetSymbolAddress((void**)&vhf, g_vhf);

    cudaFuncSetAttribute(gemm_mma<0,0>, cudaFuncAttributeMaxDynamicSharedMemorySize, SMEM_MMA);
    cudaFuncSetAttribute(gemm_mma<1,0>, cudaFuncAttributeMaxDynamicSharedMemorySize, SMEM_MMA);
    cudaFuncSetAttribute(gemm_mma<2,1>, cudaFuncAttributeMaxDynamicSharedMemorySize, SMEM_MMA);

    // 1) RoPE tables
    rope_tab_kernel<<<SEQ, 512>>>();

    // 2) convert inputs: x -> fp16; weights -> fp16 hi/lo
    conv_h      <<<(int)((size_t)M1*DIMC/1024),  256>>>(x, xf);
    conv_split_h<<<(int)((size_t)QKVN*DIMC/1024),256>>>(Wqkv_w, wqh, wql);
    conv_split_h<<<(int)((size_t)DIMC*DIMC/1024),256>>>(out_w, owh, owl);

    // 3) QKV = x @ Wqkv^T + b   [8192 x 6144 x 2048]
    gemm_mma<0,0><<<dim3(QKVN/128, M1/128, 1), 256, SMEM_MMA>>>(
        xf, wqh, wql, Wqkv_b, qkv,
        DIMC, DIMC, DIMC, QKVN, 0, 0, 0, 0, 1, 1.0f);

    // 4) RoPE: q fp16, k hi/lo fp16, k/v fp32 -> d_out
    rope_apply<<<(8 * SEQ * 512) / 256, 256>>>(qkv, qf, kh, kl, kout, vout);

    // 5) V transpose + split: Vt[b,h,d,l] hi/lo
    vt_kernel<<<dim3(SEQ/32, HDIM/32, 8), dim3(32, 8)>>>(qkv, vth, vtl);

    // 6) S = (1/32) q @ k^T  per head; causal handled by tile skip + index mask
    gemm_mma<1,0><<<dim3(SEQ/128, SEQ/128, 8), 256, SMEM_MMA>>>(
        qf, kh, kl, nullptr, S,
        HDIM, HDIM, HDIM, SEQ,
        (long)SEQ*HDIM, (long)SEQ*HDIM, (long)SEQ*SEQ, 0, 1, 0.03125f);

    // 7) causal softmax -> fp16 P (zero-fill to PV K-limit)
    softmax_h<<<8 * SEQ, 256>>>(S, pf);

    // 8) VH = P @ V (via Vt hi/lo), causal K-limit; fp16 out scattered to (B,L,D)
    gemm_mma<2,1><<<dim3(HDIM/128, SEQ/128, 8), 256, SMEM_MMA>>>(
        pf, vth, vtl, nullptr, vhf,
        SEQ, SEQ, SEQ, DIMC,
        (long)SEQ*SEQ, (long)HDIM*SEQ, (long)SEQ*DIMC, (long)HDIM, NHEADS, 1.0f);

    // 9) out = VH @ out_w^T + out_b  [8192 x 2048 x 2048]
    gemm_mma<0,0><<<dim3(DIMC/128, M1/128, 1), 256, SMEM_MMA>>>(
        vhf, owh, owl, out_b, out,
        DIMC, DIMC, DIMC, DIMC, 0, 0, 0, 0, 1, 1.0f);
}

// round 8
// speedup vs baseline: 4.1988x; 1.5240x over previous
#include <cuda_runtime.h>
#include <cuda_fp16.h>
#include <math.h>
#include <stdint.h>

// ---------------- problem constants ----------------
#define DIMC   2048
#define NHEADS 2
#define HDIM   1024
#define BATCH  4
#define SEQ    2048
#define M1     (BATCH*SEQ)   // 8192
#define QKVN   (3*DIMC)      // 6144

__device__ __forceinline__ uint32_t smem_u32(const void* p) {
    uint32_t a;
    asm("{ .reg .u64 t; cvta.to.shared.u64 t, %1; cvt.u32.u64 %0, t; }" : "=r"(a) : "l"(p));
    return a;
}

#define CP_ASYNC16(dst, src) \
    asm volatile("cp.async.cg.shared.global [%0], [%1], 16;" :: "r"(dst), "l"(src) : "memory")
#define CP_COMMIT() asm volatile("cp.async.commit_group;" ::: "memory")
#define CP_WAIT1()  asm volatile("cp.async.wait_group 1;" ::: "memory")
#define CP_WAIT0()  asm volatile("cp.async.wait_group 0;" ::: "memory")

#define LDMATRIX_X4(r0, r1, r2, r3, addr) \
    asm volatile("ldmatrix.sync.aligned.m8n8.x4.shared.b16 {%0,%1,%2,%3}, [%4];" \
        : "=r"(r0), "=r"(r1), "=r"(r2), "=r"(r3) : "r"(addr))

#define MMA_F16(c, a, b0, b1) \
    asm volatile("mma.sync.aligned.m16n8k16.row.col.f32.f16.f16.f32 " \
        "{%0,%1,%2,%3}, {%4,%5,%6,%7}, {%8,%9}, {%0,%1,%2,%3};" \
        : "+f"((c)[0]), "+f"((c)[1]), "+f"((c)[2]), "+f"((c)[3]) \
        : "r"((a)[0]), "r"((a)[1]), "r"((a)[2]), "r"((a)[3]), "r"(b0), "r"(b1))

// ---------------- scratch ----------------
__device__ float g_qkv[(size_t)M1 * QKVN];
__device__ float g_s  [(size_t)8 * SEQ * SEQ];
__device__ float g_ctab[SEQ * 512];
__device__ float g_stab[SEQ * 512];
__device__ __align__(128) __half g_xf [(size_t)M1*DIMC];
__device__ __align__(128) __half g_wqh[(size_t)QKVN*DIMC];
__device__ __align__(128) __half g_owh[(size_t)DIMC*DIMC];
__device__ __align__(128) __half g_qf [(size_t)8*SEQ*HDIM];
__device__ __align__(128) __half g_kh [(size_t)8*SEQ*HDIM];
__device__ __align__(128) __half g_vth[(size_t)8*HDIM*SEQ];
__device__ __align__(128) __half g_pf [(size_t)8*SEQ*SEQ];
__device__ __align__(128) __half g_vhf[(size_t)M1*DIMC];

// ---------------- RoPE tables ----------------
__global__ void rope_tab_kernel() {
    int idx = blockIdx.x * blockDim.x + threadIdx.x;
    int d = idx & 511, l = idx >> 9;
    double inv = exp((double)(2 * d) * (-9.210340371976184 / 1024.0));
    double th  = (double)l * inv;
    g_ctab[idx] = (float)cos(th);
    g_stab[idx] = (float)sin(th);
}

// ---------------- fp32 -> fp16 ----------------
__global__ void conv_h(const float* __restrict__ in, __half* __restrict__ o) {
    int i = blockIdx.x * 256 + threadIdx.x;
    float4 v = ((const float4*)in)[i];
    union { __half b[4]; uint2 u; } H;
    H.b[0] = __float2half_rn(v.x); H.b[1] = __float2half_rn(v.y);
    H.b[2] = __float2half_rn(v.z); H.b[3] = __float2half_rn(v.w);
    ((uint2*)o)[i] = H.u;
}

// ---------------- RoPE apply ----------------
__global__ void rope_apply(const float* __restrict__ qkv,
                           __half* __restrict__ qf, __half* __restrict__ kh,
                           float* __restrict__ kout, float* __restrict__ vout) {
    int idx = blockIdx.x * blockDim.x + threadIdx.x;
    int d = idx & 511;
    int l = (idx >> 9) & (SEQ - 1);
    int h = (idx >> 20) & 1;
    int b = idx >> 21;
    int ti = (l << 9) + d;
    float c = g_ctab[ti], s = g_stab[ti];
    const float* row = qkv + (size_t)(b * SEQ + l) * QKVN;
    int off = h * HDIM + d;
    float q1 = row[off],          q2 = row[off + 512];
    float k1 = row[DIMC + off],   k2 = row[DIMC + off + 512];
    float v1 = row[2*DIMC + off], v2 = row[2*DIMC + off + 512];
    size_t o = (size_t)((b * NHEADS + h) * SEQ + l) * HDIM + d;
    float rq1 = q1*c - q2*s, rq2 = q1*s + q2*c;
    float rk1 = k1*c - k2*s, rk2 = k1*s + k2*c;
    qf[o]       = __float2half_rn(rq1);
    qf[o + 512] = __float2half_rn(rq2);
    kh[o]       = __float2half_rn(rk1);
    kh[o + 512] = __float2half_rn(rk2);
    kout[o] = rk1; kout[o + 512] = rk2;
    vout[o] = v1;  vout[o + 512] = v2;
}

// ---------------- V transpose: qkv(v) -> Vt[b,h,d,l] fp16 ----------------
__global__ void vt_kernel(const float* __restrict__ qkv, __half* __restrict__ vth) {
    __shared__ float tile[32][33];
    int z = blockIdx.z;
    int b = z >> 1, h = z & 1;
    int l0 = blockIdx.x * 32, d0 = blockIdx.y * 32;
    int tx = threadIdx.x, ty = threadIdx.y;
    #pragma unroll
    for (int j = 0; j < 32; j += 8) {
        int l = l0 + ty + j, d = d0 + tx;
        tile[ty + j][tx] = qkv[(size_t)(b * SEQ + l) * QKVN + 2*DIMC + h*HDIM + d];
    }
    __syncthreads();
    #pragma unroll
    for (int j = 0; j < 32; j += 8) {
        int d = d0 + ty + j, l = l0 + tx;
        vth[((size_t)z * HDIM + d) * SEQ + l] = __float2half_rn(tile[tx][ty + j]);
    }
}

// ---------------- causal softmax -> fp16 P ----------------
// Row l: valid cols 0..l; cols (l, (l|127)] exact 0 (PV K-limit reads that far).
__global__ void softmax_h(const float* __restrict__ S, __half* __restrict__ P) {
    int row = blockIdx.x;
    int l = row & (SEQ - 1);
    const float* p = S + (size_t)row * SEQ;
    int t = threadIdx.x;
    int nproc = (l | 127) + 1;
    bool act = (t * 8) < nproc;

    float v[8];
    float m = -1e30f;
    if (act) {
        float4 v0 = *(const float4*)(p + t * 8);
        float4 v1 = *(const float4*)(p + t * 8 + 4);
        v[0]=v0.x; v[1]=v0.y; v[2]=v0.z; v[3]=v0.w;
        v[4]=v1.x; v[5]=v1.y; v[6]=v1.z; v[7]=v1.w;
        #pragma unroll
        for (int j = 0; j < 8; j++)
            if (t * 8 + j <= l) m = fmaxf(m, v[j]);
    }
    __shared__ float red[256];
    red[t] = m; __syncthreads();
    #pragma unroll
    for (int s = 128; s > 0; s >>= 1) { if (t < s) red[t] = fmaxf(red[t], red[t + s]); __syncthreads(); }
    float mx = red[0]; __syncthreads();

    float sum = 0.f;
    if (act) {
        #pragma unroll
        for (int j = 0; j < 8; j++) {
            v[j] = (t * 8 + j <= l) ? __expf(v[j] - mx) : 0.f;
            sum += v[j];
        }
    }
    red[t] = sum; __syncthreads();
    #pragma unroll
    for (int s = 128; s > 0; s >>= 1) { if (t < s) red[t] += red[t + s]; __syncthreads(); }
    float inv = 1.0f / red[0];

    if (act) {
        union { __half b[8]; uint4 u; } H;
        #pragma unroll
        for (int j = 0; j < 8; j++) H.b[j] = __float2half_rn(v[j] * inv);
        *(uint4*)(P + (size_t)row * SEQ + t * 8) = H.u;
    }
}

// ---------------- warp-MMA fp16 single-pass GEMM ----------------
// C = alpha*(A@B^T) (+bias). A=[M,K] K-major fp16, B=[N,K] K-major fp16.
// Block 128x128x32, 8 warps (4x2), warp tile 32x64, 3-stage cp.async.
// CAUSAL: 0 none; 1 scores: skip tiles above diag, index-mask diag tiles; 2 K-limit row0+128.
// EPI: 0 -> fp32 C0; 1 -> fp16 C0.
#define KPAD   40
#define MATB   (128 * KPAD * 2)    // 10240 B per matrix tile
#define STGB   (2 * MATB)          // 20480 B per stage (A, B)
#define NSTG   3
#define SMEM_MMA (NSTG * STGB)

__device__ __forceinline__ void load_stage_async(uint32_t sbase,
    const __half* A, const __half* B,
    int lda, int ldb, int row0, int col0, int k0)
{
    const int t = threadIdx.x;
    const __half* srcs[2] = {A, B};
    #pragma unroll
    for (int i = 0; i < 4; i++) {
        int s = t + i * 256;
        int m   = s >> 9;
        int idx = s & 511;
        int row = idx >> 2;
        int c16 = idx & 3;
        int ld  = (m == 0) ? lda : ldb;
        int r0  = (m == 0) ? row0 : col0;
        const __half* src = srcs[m] + (size_t)(r0 + row) * ld + k0 + c16 * 8;
        uint32_t dst = sbase + m * MATB + row * (KPAD * 2) + c16 * 16;
        CP_ASYNC16(dst, src);
    }
}

template<int CAUSAL, int EPI>
__global__ void __launch_bounds__(256, 1) gemm_mma(
    const __half* __restrict__ A, const __half* __restrict__ B,
    const float* __restrict__ bias,
    void* __restrict__ C0,
    int K, int lda, int ldb, int ldc,
    long sA, long sB, long sCo, long sCi, int zdiv, float alpha)
{
    extern __shared__ char smem[];
    const int tid = threadIdx.x;
    const int wid = tid >> 5;
    const int lid = tid & 31;
    const int row0 = blockIdx.y * 128;
    const int col0 = blockIdx.x * 128;
    const int bz = blockIdx.z;

    if (CAUSAL == 1 && col0 > row0) return;   // softmax never reads this region

    const size_t zoffC = (size_t)(bz / zdiv) * sCo + (size_t)(bz % zdiv) * sCi;
    A += (size_t)bz * sA;
    B += (size_t)bz * sB;

    int Keff = (CAUSAL == 2) ? min(K, row0 + 128) : K;
    const int nc = Keff >> 5;

    const uint32_t sb = smem_u32(smem);
    const int wm = (wid & 3) * 32;
    const int wn = (wid >> 2) * 64;
    const int lrow = lid & 15;
    const int lcol = (lid >> 4) << 3;

    float acc[2][8][4];
    #pragma unroll
    for (int mt = 0; mt < 2; mt++)
        #pragma unroll
        for (int nt = 0; nt < 8; nt++)
            #pragma unroll
            for (int r = 0; r < 4; r++) acc[mt][nt][r] = 0.f;

    load_stage_async(sb, A, B, lda, ldb, row0, col0, 0);
    CP_COMMIT();
    if (nc > 1) load_stage_async(sb + STGB, A, B, lda, ldb, row0, col0, 32);
    CP_COMMIT();

    for (int c = 0; c < nc; c++) {
        if (c + 1 < nc) { CP_WAIT1(); } else { CP_WAIT0(); }
        __syncthreads();
        if (c + 2 < nc) {
            load_stage_async(sb + ((c + 2) % NSTG) * STGB, A, B,
                             lda, ldb, row0, col0, (c + 2) << 5);
            CP_COMMIT();
        }

        uint32_t stg = sb + (c % NSTG) * STGB;
        #pragma unroll
        for (int kk = 0; kk < 32; kk += 16) {
            uint32_t af[2][4], bf[4][4];
            #pragma unroll
            for (int mt = 0; mt < 2; mt++) {
                uint32_t ra = stg + ((wm + mt * 16 + lrow) * KPAD + kk + lcol) * 2;
                LDMATRIX_X4(af[mt][0], af[mt][1], af[mt][2], af[mt][3], ra);
            }
            #pragma unroll
            for (int g = 0; g < 4; g++) {
                uint32_t rb = stg + MATB + ((wn + g * 16 + lrow) * KPAD + kk + lcol) * 2;
                LDMATRIX_X4(bf[g][0], bf[g][1], bf[g][2], bf[g][3], rb);
            }
            #pragma unroll
            for (int mt = 0; mt < 2; mt++)
                #pragma unroll
                for (int nt = 0; nt < 8; nt++) {
                    int g = nt >> 1, o = nt & 1;
                    MMA_F16(acc[mt][nt], af[mt], bf[g][o], bf[g][o + 2]);
                }
        }
        __syncthreads();
    }

    // ---------------- epilogue ----------------
    #pragma unroll
    for (int mt = 0; mt < 2; mt++) {
        #pragma unroll
        for (int nt = 0; nt < 8; nt++) {
            int gr0 = row0 + wm + mt * 16 + (lid >> 2);
            int gc  = col0 + wn + nt * 8 + (lid & 3) * 2;
            #pragma unroll
            for (int half = 0; half < 2; half++) {
                int gr = gr0 + half * 8;
                float v0 = acc[mt][nt][2 * half]     * alpha;
                float v1 = acc[mt][nt][2 * half + 1] * alpha;
                if (bias) { v0 += bias[gc]; v1 += bias[gc + 1]; }
                if (CAUSAL == 1 && row0 == col0) {   // diagonal tile: index mask
                    if (gc     > gr) v0 = -1e9f;
                    if (gc + 1 > gr) v1 = -1e9f;
                }
                if (EPI == 0) {
                    float* C = (float*)C0 + zoffC + (size_t)gr * ldc + gc;
                    *(float2*)C = make_float2(v0, v1);
                } else {
                    __half* C = (__half*)C0 + zoffC + (size_t)gr * ldc + gc;
                    union { __half b[2]; uint32_t u; } H;
                    H.b[0] = __float2half_rn(v0);
                    H.b[1] = __float2half_rn(v1);
                    *(uint32_t*)C = H.u;
                }
            }
        }
    }
}

// ---------------- launch ----------------
extern "C" void kernel_launch(void* const* d_in, const int* in_sizes, int n_in,
                              void* d_out, int out_size) {
    const float* x      = (const float*)d_in[0];
    const float* Wqkv_w = (const float*)d_in[2];
    const float* Wqkv_b = (const float*)d_in[3];
    const float* out_w  = (const float*)d_in[4];
    const float* out_b  = (const float*)d_in[5];

    float* out  = (float*)d_out;
    float* kout = out  + (size_t)M1 * DIMC;
    float* vout = kout + (size_t)8 * SEQ * HDIM;

    float *qkv, *S;
    __half *xf,*wqh,*owh,*qf,*kh,*vth,*pf,*vhf;
    cudaGetSymbolAddress((void**)&qkv, g_qkv);
    cudaGetSymbolAddress((void**)&S,   g_s);
    cudaGetSymbolAddress((void**)&xf,  g_xf);
    cudaGetSymbolAddress((void**)&wqh, g_wqh);
    cudaGetSymbolAddress((void**)&owh, g_owh);
    cudaGetSymbolAddress((void**)&qf,  g_qf);
    cudaGetSymbolAddress((void**)&kh,  g_kh);
    cudaGetSymbolAddress((void**)&vth, g_vth);
    cudaGetSymbolAddress((void**)&pf,  g_pf);
    cudaGetSymbolAddress((void**)&vhf, g_vhf);

    cudaFuncSetAttribute(gemm_mma<0,0>, cudaFuncAttributeMaxDynamicSharedMemorySize, SMEM_MMA);
    cudaFuncSetAttribute(gemm_mma<1,0>, cudaFuncAttributeMaxDynamicSharedMemorySize, SMEM_MMA);
    cudaFuncSetAttribute(gemm_mma<2,1>, cudaFuncAttributeMaxDynamicSharedMemorySize, SMEM_MMA);

    // 1) RoPE tables
    rope_tab_kernel<<<SEQ, 512>>>();

    // 2) convert inputs to fp16
    conv_h<<<(int)((size_t)M1*DIMC/1024),  256>>>(x, xf);
    conv_h<<<(int)((size_t)QKVN*DIMC/1024),256>>>(Wqkv_w, wqh);
    conv_h<<<(int)((size_t)DIMC*DIMC/1024),256>>>(out_w, owh);

    // 3) QKV = x @ Wqkv^T + b   [8192 x 6144 x 2048]
    gemm_mma<0,0><<<dim3(QKVN/128, M1/128, 1), 256, SMEM_MMA>>>(
        xf, wqh, Wqkv_b, qkv,
        DIMC, DIMC, DIMC, QKVN, 0, 0, 0, 0, 1, 1.0f);

    // 4) RoPE: q/k fp16, k/v fp32 -> d_out
    rope_apply<<<(8 * SEQ * 512) / 256, 256>>>(qkv, qf, kh, kout, vout);

    // 5) V transpose: Vt[b,h,d,l] fp16
    vt_kernel<<<dim3(SEQ/32, HDIM/32, 8), dim3(32, 8)>>>(qkv, vth);

    // 6) S = (1/32) q @ k^T  per head; causal via tile skip + index mask
    gemm_mma<1,0><<<dim3(SEQ/128, SEQ/128, 8), 256, SMEM_MMA>>>(
        qf, kh, nullptr, S,
        HDIM, HDIM, HDIM, SEQ,
        (long)SEQ*HDIM, (long)SEQ*HDIM, (long)SEQ*SEQ, 0, 1, 0.03125f);

    // 7) causal softmax -> fp16 P (zero-fill to PV K-limit)
    softmax_h<<<8 * SEQ, 256>>>(S, pf);

    // 8) VH = P @ V (via Vt), causal K-limit; fp16 out scattered to (B,L,D)
    gemm_mma<2,1><<<dim3(HDIM/128, SEQ/128, 8), 256, SMEM_MMA>>>(
        pf, vth, nullptr, vhf,
        SEQ, SEQ, SEQ, DIMC,
        (long)SEQ*SEQ, (long)HDIM*SEQ, (long)SEQ*DIMC, (long)HDIM, NHEADS, 1.0f);

    // 9) out = VH @ out_w^T + out_b  [8192 x 2048 x 2048]
    gemm_mma<0,0><<<dim3(DIMC/128, M1/128, 1), 256, SMEM_MMA>>>(
        vhf, owh, out_b, out,
        DIMC, DIMC, DIMC, DIMC, 0, 0, 0, 0, 1, 1.0f);
}

// round 9
// speedup vs baseline: 5.3944x; 1.2847x over previous
#include <cuda_runtime.h>
#include <cuda_fp16.h>
#include <math.h>
#include <stdint.h>

// ---------------- problem constants ----------------
#define DIMC   2048
#define NHEADS 2
#define HDIM   1024
#define BATCH  4
#define SEQ    2048
#define M1     (BATCH*SEQ)   // 8192
#define QKVN   (3*DIMC)      // 6144

__device__ __forceinline__ uint32_t smem_u32(const void* p) {
    uint32_t a;
    asm("{ .reg .u64 t; cvta.to.shared.u64 t, %1; cvt.u32.u64 %0, t; }" : "=r"(a) : "l"(p));
    return a;
}

#define CP_ASYNC16(dst, src) \
    asm volatile("cp.async.cg.shared.global [%0], [%1], 16;" :: "r"(dst), "l"(src) : "memory")
#define CP_COMMIT() asm volatile("cp.async.commit_group;" ::: "memory")
#define CP_WAIT1()  asm volatile("cp.async.wait_group 1;" ::: "memory")
#define CP_WAIT0()  asm volatile("cp.async.wait_group 0;" ::: "memory")

#define LDMATRIX_X4(r0, r1, r2, r3, addr) \
    asm volatile("ldmatrix.sync.aligned.m8n8.x4.shared.b16 {%0,%1,%2,%3}, [%4];" \
        : "=r"(r0), "=r"(r1), "=r"(r2), "=r"(r3) : "r"(addr))

#define MMA_F16(c, a, b0, b1) \
    asm volatile("mma.sync.aligned.m16n8k16.row.col.f32.f16.f16.f32 " \
        "{%0,%1,%2,%3}, {%4,%5,%6,%7}, {%8,%9}, {%0,%1,%2,%3};" \
        : "+f"((c)[0]), "+f"((c)[1]), "+f"((c)[2]), "+f"((c)[3]) \
        : "r"((a)[0]), "r"((a)[1]), "r"((a)[2]), "r"((a)[3]), "r"(b0), "r"(b1))

// ---------------- scratch ----------------
__device__ float g_qkv[(size_t)M1 * QKVN];
__device__ float g_s  [(size_t)8 * SEQ * SEQ];
__device__ float g_ctab[SEQ * 512];
__device__ float g_stab[SEQ * 512];
__device__ __align__(128) __half g_xf [(size_t)M1*DIMC];
__device__ __align__(128) __half g_wqh[(size_t)QKVN*DIMC];
__device__ __align__(128) __half g_owh[(size_t)DIMC*DIMC];
__device__ __align__(128) __half g_qf [(size_t)8*SEQ*HDIM];
__device__ __align__(128) __half g_kh [(size_t)8*SEQ*HDIM];
__device__ __align__(128) __half g_vth[(size_t)8*HDIM*SEQ];
__device__ __align__(128) __half g_pf [(size_t)8*SEQ*SEQ];
__device__ __align__(128) __half g_vhf[(size_t)M1*DIMC];

// ---------------- RoPE tables (fp32, matches reference dtype math) ----------------
__global__ void rope_tab_kernel() {
    int idx = blockIdx.x * blockDim.x + threadIdx.x;
    int d = idx & 511, l = idx >> 9;
    // reference: inv = exp(2d * (-log(10000)/1024)) in float32
    float inv = expf((float)(2 * d) * (-9.210340371976184f / 1024.0f));
    float th  = (float)l * inv;
    g_ctab[idx] = cosf(th);
    g_stab[idx] = sinf(th);
}

// ---------------- fp32 -> fp16 ----------------
__global__ void conv_h(const float* __restrict__ in, __half* __restrict__ o) {
    int i = blockIdx.x * 256 + threadIdx.x;
    float4 v = ((const float4*)in)[i];
    union { __half b[4]; uint2 u; } H;
    H.b[0] = __float2half_rn(v.x); H.b[1] = __float2half_rn(v.y);
    H.b[2] = __float2half_rn(v.z); H.b[3] = __float2half_rn(v.w);
    ((uint2*)o)[i] = H.u;
}

// ---------------- RoPE apply ----------------
__global__ void rope_apply(const float* __restrict__ qkv,
                           __half* __restrict__ qf, __half* __restrict__ kh,
                           float* __restrict__ kout, float* __restrict__ vout) {
    int idx = blockIdx.x * blockDim.x + threadIdx.x;
    int d = idx & 511;
    int l = (idx >> 9) & (SEQ - 1);
    int h = (idx >> 20) & 1;
    int b = idx >> 21;
    int ti = (l << 9) + d;
    float c = g_ctab[ti], s = g_stab[ti];
    const float* row = qkv + (size_t)(b * SEQ + l) * QKVN;
    int off = h * HDIM + d;
    float q1 = row[off],          q2 = row[off + 512];
    float k1 = row[DIMC + off],   k2 = row[DIMC + off + 512];
    float v1 = row[2*DIMC + off], v2 = row[2*DIMC + off + 512];
    size_t o = (size_t)((b * NHEADS + h) * SEQ + l) * HDIM + d;
    float rq1 = q1*c - q2*s, rq2 = q1*s + q2*c;
    float rk1 = k1*c - k2*s, rk2 = k1*s + k2*c;
    qf[o]       = __float2half_rn(rq1);
    qf[o + 512] = __float2half_rn(rq2);
    kh[o]       = __float2half_rn(rk1);
    kh[o + 512] = __float2half_rn(rk2);
    kout[o] = rk1; kout[o + 512] = rk2;
    vout[o] = v1;  vout[o + 512] = v2;
}

// ---------------- V transpose: qkv(v) -> Vt[b,h,d,l] fp16 ----------------
__global__ void vt_kernel(const float* __restrict__ qkv, __half* __restrict__ vth) {
    __shared__ float tile[32][33];
    int z = blockIdx.z;
    int b = z >> 1, h = z & 1;
    int l0 = blockIdx.x * 32, d0 = blockIdx.y * 32;
    int tx = threadIdx.x, ty = threadIdx.y;
    #pragma unroll
    for (int j = 0; j < 32; j += 8) {
        int l = l0 + ty + j, d = d0 + tx;
        tile[ty + j][tx] = qkv[(size_t)(b * SEQ + l) * QKVN + 2*DIMC + h*HDIM + d];
    }
    __syncthreads();
    #pragma unroll
    for (int j = 0; j < 32; j += 8) {
        int d = d0 + ty + j, l = l0 + tx;
        vth[((size_t)z * HDIM + d) * SEQ + l] = __float2half_rn(tile[tx][ty + j]);
    }
}

// ---------------- causal softmax -> fp16 P ----------------
__global__ void softmax_h(const float* __restrict__ S, __half* __restrict__ P) {
    int row = blockIdx.x;
    int l = row & (SEQ - 1);
    const float* p = S + (size_t)row * SEQ;
    int t = threadIdx.x;
    int nproc = (l | 127) + 1;
    bool act = (t * 8) < nproc;

    float v[8];
    float m = -1e30f;
    if (act) {
        float4 v0 = *(const float4*)(p + t * 8);
        float4 v1 = *(const float4*)(p + t * 8 + 4);
        v[0]=v0.x; v[1]=v0.y; v[2]=v0.z; v[3]=v0.w;
        v[4]=v1.x; v[5]=v1.y; v[6]=v1.z; v[7]=v1.w;
        #pragma unroll
        for (int j = 0; j < 8; j++)
            if (t * 8 + j <= l) m = fmaxf(m, v[j]);
    }
    __shared__ float red[256];
    red[t] = m; __syncthreads();
    #pragma unroll
    for (int s = 128; s > 0; s >>= 1) { if (t < s) red[t] = fmaxf(red[t], red[t + s]); __syncthreads(); }
    float mx = red[0]; __syncthreads();

    float sum = 0.f;
    if (act) {
        #pragma unroll
        for (int j = 0; j < 8; j++) {
            v[j] = (t * 8 + j <= l) ? __expf(v[j] - mx) : 0.f;
            sum += v[j];
        }
    }
    red[t] = sum; __syncthreads();
    #pragma unroll
    for (int s = 128; s > 0; s >>= 1) { if (t < s) red[t] += red[t + s]; __syncthreads(); }
    float inv = 1.0f / red[0];

    if (act) {
        union { __half b[8]; uint4 u; } H;
        #pragma unroll
        for (int j = 0; j < 8; j++) H.b[j] = __float2half_rn(v[j] * inv);
        *(uint4*)(P + (size_t)row * SEQ + t * 8) = H.u;
    }
}

// ---------------- warp-MMA fp16 single-pass GEMM (occupancy 2) ----------------
// C = alpha*(A@B^T) (+bias). A=[M,K] K-major fp16, B=[N,K] K-major fp16.
// Block 128x128x32, 8 warps (4x2), warp tile 32x64, 3-stage cp.async, 2 CTAs/SM.
#define KPAD   40
#define MATB   (128 * KPAD * 2)
#define STGB   (2 * MATB)
#define NSTG   3
#define SMEM_MMA (NSTG * STGB)

__device__ __forceinline__ void load_stage_async(uint32_t sbase,
    const __half* A, const __half* B,
    int lda, int ldb, int row0, int col0, int k0)
{
    const int t = threadIdx.x;
    const __half* srcs[2] = {A, B};
    #pragma unroll
    for (int i = 0; i < 4; i++) {
        int s = t + i * 256;
        int m   = s >> 9;
        int idx = s & 511;
        int row = idx >> 2;
        int c16 = idx & 3;
        int ld  = (m == 0) ? lda : ldb;
        int r0  = (m == 0) ? row0 : col0;
        const __half* src = srcs[m] + (size_t)(r0 + row) * ld + k0 + c16 * 8;
        uint32_t dst = sbase + m * MATB + row * (KPAD * 2) + c16 * 16;
        CP_ASYNC16(dst, src);
    }
}

template<int CAUSAL, int EPI>
__global__ void __launch_bounds__(256, 2) gemm_mma(
    const __half* __restrict__ A, const __half* __restrict__ B,
    const float* __restrict__ bias,
    void* __restrict__ C0,
    int K, int lda, int ldb, int ldc,
    long sA, long sB, long sCo, long sCi, int zdiv, float alpha)
{
    extern __shared__ char smem[];
    const int tid = threadIdx.x;
    const int wid = tid >> 5;
    const int lid = tid & 31;
    const int row0 = blockIdx.y * 128;
    const int col0 = blockIdx.x * 128;
    const int bz = blockIdx.z;

    if (CAUSAL == 1 && col0 > row0) return;   // softmax never reads this region

    const size_t zoffC = (size_t)(bz / zdiv) * sCo + (size_t)(bz % zdiv) * sCi;
    A += (size_t)bz * sA;
    B += (size_t)bz * sB;

    int Keff = (CAUSAL == 2) ? min(K, row0 + 128) : K;
    const int nc = Keff >> 5;

    const uint32_t sb = smem_u32(smem);
    const int wm = (wid & 3) * 32;
    const int wn = (wid >> 2) * 64;
    const int lrow = lid & 15;
    const int lcol = (lid >> 4) << 3;

    float acc[2][8][4];
    #pragma unroll
    for (int mt = 0; mt < 2; mt++)
        #pragma unroll
        for (int nt = 0; nt < 8; nt++)
            #pragma unroll
            for (int r = 0; r < 4; r++) acc[mt][nt][r] = 0.f;

    load_stage_async(sb, A, B, lda, ldb, row0, col0, 0);
    CP_COMMIT();
    if (nc > 1) load_stage_async(sb + STGB, A, B, lda, ldb, row0, col0, 32);
    CP_COMMIT();

    for (int c = 0; c < nc; c++) {
        if (c + 1 < nc) { CP_WAIT1(); } else { CP_WAIT0(); }
        __syncthreads();
        if (c + 2 < nc) {
            load_stage_async(sb + ((c + 2) % NSTG) * STGB, A, B,
                             lda, ldb, row0, col0, (c + 2) << 5);
            CP_COMMIT();
        }

        uint32_t stg = sb + (c % NSTG) * STGB;
        #pragma unroll
        for (int kk = 0; kk < 32; kk += 16) {
            uint32_t af[2][4], bf[4][4];
            #pragma unroll
            for (int mt = 0; mt < 2; mt++) {
                uint32_t ra = stg + ((wm + mt * 16 + lrow) * KPAD + kk + lcol) * 2;
                LDMATRIX_X4(af[mt][0], af[mt][1], af[mt][2], af[mt][3], ra);
            }
            #pragma unroll
            for (int g = 0; g < 4; g++) {
                uint32_t rb = stg + MATB + ((wn + g * 16 + lrow) * KPAD + kk + lcol) * 2;
                LDMATRIX_X4(bf[g][0], bf[g][1], bf[g][2], bf[g][3], rb);
            }
            #pragma unroll
            for (int mt = 0; mt < 2; mt++)
                #pragma unroll
                for (int nt = 0; nt < 8; nt++) {
                    int g = nt >> 1, o = nt & 1;
                    MMA_F16(acc[mt][nt], af[mt], bf[g][o], bf[g][o + 2]);
                }
        }
        __syncthreads();
    }

    // ---------------- epilogue ----------------
    #pragma unroll
    for (int mt = 0; mt < 2; mt++) {
        #pragma unroll
        for (int nt = 0; nt < 8; nt++) {
            int gr0 = row0 + wm + mt * 16 + (lid >> 2);
            int gc  = col0 + wn + nt * 8 + (lid & 3) * 2;
            #pragma unroll
            for (int half = 0; half < 2; half++) {
                int gr = gr0 + half * 8;
                float v0 = acc[mt][nt][2 * half]     * alpha;
                float v1 = acc[mt][nt][2 * half + 1] * alpha;
                if (bias) { v0 += bias[gc]; v1 += bias[gc + 1]; }
                if (CAUSAL == 1 && row0 == col0) {
                    if (gc     > gr) v0 = -1e9f;
                    if (gc + 1 > gr) v1 = -1e9f;
                }
                if (EPI == 0) {
                    float* C = (float*)C0 + zoffC + (size_t)gr * ldc + gc;
                    *(float2*)C = make_float2(v0, v1);
                } else {
                    __half* C = (__half*)C0 + zoffC + (size_t)gr * ldc + gc;
                    union { __half b[2]; uint32_t u; } H;
                    H.b[0] = __float2half_rn(v0);
                    H.b[1] = __float2half_rn(v1);
                    *(uint32_t*)C = H.u;
                }
            }
        }
    }
}

// ---------------- launch ----------------
extern "C" void kernel_launch(void* const* d_in, const int* in_sizes, int n_in,
                              void* d_out, int out_size) {
    const float* x      = (const float*)d_in[0];
    const float* Wqkv_w = (const float*)d_in[2];
    const float* Wqkv_b = (const float*)d_in[3];
    const float* out_w  = (const float*)d_in[4];
    const float* out_b  = (const float*)d_in[5];

    float* out  = (float*)d_out;
    float* kout = out  + (size_t)M1 * DIMC;
    float* vout = kout + (size_t)8 * SEQ * HDIM;

    float *qkv, *S;
    __half *xf,*wqh,*owh,*qf,*kh,*vth,*pf,*vhf;
    cudaGetSymbolAddress((void**)&qkv, g_qkv);
    cudaGetSymbolAddress((void**)&S,   g_s);
    cudaGetSymbolAddress((void**)&xf,  g_xf);
    cudaGetSymbolAddress((void**)&wqh, g_wqh);
    cudaGetSymbolAddress((void**)&owh, g_owh);
    cudaGetSymbolAddress((void**)&qf,  g_qf);
    cudaGetSymbolAddress((void**)&kh,  g_kh);
    cudaGetSymbolAddress((void**)&vth, g_vth);
    cudaGetSymbolAddress((void**)&pf,  g_pf);
    cudaGetSymbolAddress((void**)&vhf, g_vhf);

    cudaFuncSetAttribute(gemm_mma<0,0>, cudaFuncAttributeMaxDynamicSharedMemorySize, SMEM_MMA);
    cudaFuncSetAttribute(gemm_mma<1,0>, cudaFuncAttributeMaxDynamicSharedMemorySize, SMEM_MMA);
    cudaFuncSetAttribute(gemm_mma<2,1>, cudaFuncAttributeMaxDynamicSharedMemorySize, SMEM_MMA);

    // 1) RoPE tables (fp32)
    rope_tab_kernel<<<SEQ, 512>>>();

    // 2) convert inputs to fp16
    conv_h<<<(int)((size_t)M1*DIMC/1024),  256>>>(x, xf);
    conv_h<<<(int)((size_t)QKVN*DIMC/1024),256>>>(Wqkv_w, wqh);
    conv_h<<<(int)((size_t)DIMC*DIMC/1024),256>>>(out_w, owh);

    // 3) QKV = x @ Wqkv^T + b   [8192 x 6144 x 2048]
    gemm_mma<0,0><<<dim3(QKVN/128, M1/128, 1), 256, SMEM_MMA>>>(
        xf, wqh, Wqkv_b, qkv,
        DIMC, DIMC, DIMC, QKVN, 0, 0, 0, 0, 1, 1.0f);

    // 4) RoPE: q/k fp16, k/v fp32 -> d_out
    rope_apply<<<(8 * SEQ * 512) / 256, 256>>>(qkv, qf, kh, kout, vout);

    // 5) V transpose: Vt[b,h,d,l] fp16
    vt_kernel<<<dim3(SEQ/32, HDIM/32, 8), dim3(32, 8)>>>(qkv, vth);

    // 6) S = (1/32) q @ k^T  per head; causal via tile skip + index mask
    gemm_mma<1,0><<<dim3(SEQ/128, SEQ/128, 8), 256, SMEM_MMA>>>(
        qf, kh, nullptr, S,
        HDIM, HDIM, HDIM, SEQ,
        (long)SEQ*HDIM, (long)SEQ*HDIM, (long)SEQ*SEQ, 0, 1, 0.03125f);

    // 7) causal softmax -> fp16 P (zero-fill to PV K-limit)
    softmax_h<<<8 * SEQ, 256>>>(S, pf);

    // 8) VH = P @ V (via Vt), causal K-limit; fp16 out scattered to (B,L,D)
    gemm_mma<2,1><<<dim3(HDIM/128, SEQ/128, 8), 256, SMEM_MMA>>>(
        pf, vth, nullptr, vhf,
        SEQ, SEQ, SEQ, DIMC,
        (long)SEQ*SEQ, (long)HDIM*SEQ, (long)SEQ*DIMC, (long)HDIM, NHEADS, 1.0f);

    // 9) out = VH @ out_w^T + out_b  [8192 x 2048 x 2048]
    gemm_mma<0,0><<<dim3(DIMC/128, M1/128, 1), 256, SMEM_MMA>>>(
        vhf, owh, out_b, out,
        DIMC, DIMC, DIMC, DIMC, 0, 0, 0, 0, 1, 1.0f);
}